// round 11
// baseline (speedup 1.0000x reference)
#include <cuda_runtime.h>
#include <cuda_bf16.h>
#include <cstdint>
#include <math.h>

// Problem constants (fixed by the dataset)
#define NN   100000
#define EE   1600000
#define F_IN 128
#define HID  256
#define NC   64
#define NBLK ((NN + 255) / 256)   // 391

// ---------------------------------------------------------------------------
// Scratch (static __device__ arrays — no allocation allowed)
// ---------------------------------------------------------------------------
__device__ float g_deg[NN];
__device__ float g_dinv[NN];
__device__ int   g_wptr[NN];
__device__ int   g_rowptr[NN + 1];
__device__ int   g_blksum[NBLK];
__device__ int   g_blkoff[NBLK];
__device__ int   g_csrc[EE];
__device__ float g_cnorm[EE];
__device__ __align__(16) float         g_bufA[(size_t)NN * HID];   // GEMM fp32 out
__device__ __align__(16) __nv_bfloat16 g_hi[(size_t)NN * HID];     // activations hi
__device__ __align__(16) __nv_bfloat16 g_lo[(size_t)NN * HID];     // activations lo
__device__ __align__(16) __nv_bfloat16 g_xhi[(size_t)NN * F_IN];   // agg(x) hi
__device__ __align__(16) __nv_bfloat16 g_xlo[(size_t)NN * F_IN];   // agg(x) lo
__device__ __align__(16) __nv_bfloat16 g_w0hi[HID * F_IN], g_w0lo[HID * F_IN];
__device__ __align__(16) __nv_bfloat16 g_w1hi[HID * HID],  g_w1lo[HID * HID];
__device__ __align__(16) __nv_bfloat16 g_w2hi[NC * HID],   g_w2lo[NC * HID];

// ---------------------------------------------------------------------------
// PTX helpers (portable sm_80+; works on generic sm_103 target)
// ---------------------------------------------------------------------------
__device__ __forceinline__ uint32_t smem_u32(const void* p) {
    uint32_t a;
    asm("{ .reg .u64 t; cvta.to.shared.u64 t, %1; cvt.u32.u64 %0, t; }"
        : "=r"(a) : "l"(p));
    return a;
}

#define LDSM4(r, addr) \
    asm volatile("ldmatrix.sync.aligned.m8n8.x4.shared.b16 {%0,%1,%2,%3}, [%4];" \
        : "=r"((r)[0]), "=r"((r)[1]), "=r"((r)[2]), "=r"((r)[3]) : "r"(addr))

#define MMA_BF16(c, a, b0, b1) \
    asm volatile("mma.sync.aligned.m16n8k16.row.col.f32.bf16.bf16.f32 " \
        "{%0,%1,%2,%3}, {%4,%5,%6,%7}, {%8,%9}, {%0,%1,%2,%3};" \
        : "+f"((c)[0]), "+f"((c)[1]), "+f"((c)[2]), "+f"((c)[3]) \
        : "r"((a)[0]), "r"((a)[1]), "r"((a)[2]), "r"((a)[3]), "r"(b0), "r"(b1))

#define CP16(dst, src, sz) \
    asm volatile("cp.async.cg.shared.global [%0], [%1], 16, %2;" \
        :: "r"(dst), "l"(src), "r"(sz) : "memory")
#define CP_COMMIT() asm volatile("cp.async.commit_group;" ::: "memory")
template <int N>
__device__ __forceinline__ void cp_wait() {
    asm volatile("cp.async.wait_group %0;" :: "n"(N) : "memory");
}

// ---------------------------------------------------------------------------
// Preprocessing kernels
// ---------------------------------------------------------------------------
__global__ void k_init()
{
    int i = blockIdx.x * blockDim.x + threadIdx.x;
    if (i < NN) { g_deg[i] = 1.0f; g_wptr[i] = 0; }
}

__global__ void k_deg_count(const int* __restrict__ dst, const float* __restrict__ w)
{
    int e = blockIdx.x * blockDim.x + threadIdx.x;
    if (e < EE) {
        int d = dst[e];
        atomicAdd(&g_deg[d], w[e]);
        atomicAdd(&g_wptr[d], 1);
    }
}

// blocksum of counts + dinv (fused: same index space)
__global__ void k_blocksum_dinv()
{
    __shared__ int sh[256];
    int i = blockIdx.x * 256 + threadIdx.x;
    sh[threadIdx.x] = (i < NN) ? g_wptr[i] : 0;
    if (i < NN) g_dinv[i] = rsqrtf(g_deg[i]);
    __syncthreads();
    for (int o = 128; o > 0; o >>= 1) {
        if (threadIdx.x < o) sh[threadIdx.x] += sh[threadIdx.x + o];
        __syncthreads();
    }
    if (threadIdx.x == 0) g_blksum[blockIdx.x] = sh[0];
}

__global__ void k_scanblk()
{
    __shared__ int sh[512];
    int t = threadIdx.x;
    int v = (t < NBLK) ? g_blksum[t] : 0;
    sh[t] = v;
    __syncthreads();
    for (int o = 1; o < 512; o <<= 1) {
        int a = (t >= o) ? sh[t - o] : 0;
        __syncthreads();
        sh[t] += a;
        __syncthreads();
    }
    if (t < NBLK) g_blkoff[t] = sh[t] - v;   // exclusive
}

__global__ void k_rowptr()
{
    __shared__ int sh[256];
    int i = blockIdx.x * 256 + threadIdx.x;
    int v = (i < NN) ? g_wptr[i] : 0;
    sh[threadIdx.x] = v;
    __syncthreads();
    for (int o = 1; o < 256; o <<= 1) {
        int a = (threadIdx.x >= o) ? sh[threadIdx.x - o] : 0;
        __syncthreads();
        sh[threadIdx.x] += a;
        __syncthreads();
    }
    if (i < NN) {
        int off = g_blkoff[blockIdx.x] + sh[threadIdx.x] - v;
        g_rowptr[i] = off;
        g_wptr[i]   = off;   // write cursor for fill
    }
    if (i == NN - 1) g_rowptr[NN] = EE;
}

__global__ void k_fill(const int* __restrict__ src, const int* __restrict__ dst,
                       const float* __restrict__ w)
{
    int e = blockIdx.x * blockDim.x + threadIdx.x;
    if (e < EE) {
        int s = src[e], d = dst[e];
        float nm = g_dinv[s] * w[e] * g_dinv[d];
        int slot = atomicAdd(&g_wptr[d], 1);
        g_csrc[slot]  = s;
        g_cnorm[slot] = nm;
    }
}

// All three weights: W[K,N] row-major -> Wt[N,K] K-major, split hi/lo (fused)
__global__ void k_wsplit_all(const float* __restrict__ W0,
                             const float* __restrict__ W1,
                             const float* __restrict__ W2)
{
    int i = blockIdx.x * blockDim.x + threadIdx.x;
    const float* W; __nv_bfloat16 *thi, *tlo; int K, Ncols, j;
    if (i < F_IN * HID)                   { W = W0; thi = g_w0hi; tlo = g_w0lo; K = F_IN; Ncols = HID; j = i; }
    else if (i < F_IN * HID + HID * HID)  { W = W1; thi = g_w1hi; tlo = g_w1lo; K = HID;  Ncols = HID; j = i - F_IN * HID; }
    else if (i < F_IN * HID + HID * HID + HID * NC)
                                          { W = W2; thi = g_w2hi; tlo = g_w2lo; K = HID;  Ncols = NC;  j = i - F_IN * HID - HID * HID; }
    else return;
    int n = j / K, k = j % K;
    float v = W[k * Ncols + n];
    __nv_bfloat16 h = __float2bfloat16(v);
    thi[j] = h;
    tlo[j] = __float2bfloat16(v - __bfloat162float(h));
}

// ---------------------------------------------------------------------------
// HMMA split-bf16 GEMM, cp.async 3-stage pipelined.
//   C[M, ldc] = A[M, KT] @ Bt[Ncols, KT]^T ; 3 terms Ah*Bh + Ah*Bl + Al*Bh.
//   BM=128, BN=64, BK=32, 256 threads (warps 4m x 2n, warp tile 32x32).
//   Smem: 3 stages x 24576 B (dynamic), 64 B rows, XOR-16B swizzle.
//   EPI=0: fp32 store. EPI=1: bias+relu+hi/lo bf16.
// ---------------------------------------------------------------------------
template <int EPI>
__global__ void __launch_bounds__(256)
gemm_mma(int M, int KT,
         const __nv_bfloat16* __restrict__ Ahi, const __nv_bfloat16* __restrict__ Alo,
         const __nv_bfloat16* __restrict__ Bhi, const __nv_bfloat16* __restrict__ Blo,
         float* __restrict__ Cf,
         __nv_bfloat16* __restrict__ Chi, __nv_bfloat16* __restrict__ Clo,
         const float* __restrict__ bias, int ldc)
{
    constexpr int STG = 24576;          // (128*2 + 64*2) rows * 64 B
    constexpr int OFF_AH = 0, OFF_AL = 8192, OFF_BH = 16384, OFF_BL = 20480;

    extern __shared__ __align__(16) char sm[];
    const uint32_t smb = smem_u32(sm);

    const int tid  = threadIdx.x;
    const int lane = tid & 31, wid = tid >> 5;
    const int wm = wid & 3;             // 0..3  (m)
    const int wn = wid >> 2;            // 0..1  (n)
    const int rowBase = blockIdx.y * 128;
    const int colBase = blockIdx.x * 64;

    float c[2][4][4];
    #pragma unroll
    for (int mi = 0; mi < 2; mi++)
        #pragma unroll
        for (int nf = 0; nf < 4; nf++)
            #pragma unroll
            for (int j = 0; j < 4; j++) c[mi][nf][j] = 0.f;

    // ldmatrix per-lane rows + swizzle keys
    const int lane15 = lane & 15;
    int  rA[2], rB[2];
    rA[0] = wm * 32 + lane15;  rA[1] = rA[0] + 16;
    rB[0] = wn * 32 + lane15;  rB[1] = rB[0] + 16;
    const int swA0 = (rA[0] >> 1) & 3, swA1 = (rA[1] >> 1) & 3;
    const int swB0 = (rB[0] >> 1) & 3, swB1 = (rB[1] >> 1) & 3;
    const int ccB  = lane >> 4;

    const int nchunk = KT >> 5;

    // ---- tile loader (cp.async) ----
    auto ld_tiles = [&](int st, int ch) {
        const uint32_t sb = smb + st * STG;
        const int k0 = ch * 32;
        #pragma unroll
        for (int i = tid; i < 512; i += 256) {      // A: 128 rows x 4 chunks
            int row = i >> 2, cc = i & 3;
            int gr  = rowBase + row;
            uint32_t sz = (gr < M) ? 16u : 0u;
            int gra = (gr < M) ? gr : (M - 1);
            size_t go = (size_t)gra * KT + k0 + cc * 8;
            uint32_t d = row * 64 + (((cc ^ ((row >> 1) & 3))) << 4);
            CP16(sb + OFF_AH + d, (const char*)(Ahi + go), sz);
            CP16(sb + OFF_AL + d, (const char*)(Alo + go), sz);
        }
        {                                            // B: 64 rows x 4 chunks
            int row = tid >> 2, cc = tid & 3;
            size_t go = (size_t)(colBase + row) * KT + k0 + cc * 8;
            uint32_t d = row * 64 + (((cc ^ ((row >> 1) & 3))) << 4);
            CP16(sb + OFF_BH + d, (const char*)(Bhi + go), 16u);
            CP16(sb + OFF_BL + d, (const char*)(Blo + go), 16u);
        }
    };

    ld_tiles(0, 0); CP_COMMIT();
    ld_tiles(1, 1); CP_COMMIT();

    int st = 0;
    for (int ch = 0; ch < nchunk; ch++) {
        if (ch + 1 < nchunk) cp_wait<1>(); else cp_wait<0>();
        __syncthreads();
        if (ch + 2 < nchunk) {
            int st2 = st + 2; if (st2 >= 3) st2 -= 3;
            ld_tiles(st2, ch + 2);
            CP_COMMIT();
        }

        const uint32_t sb = smb + st * STG;
        #pragma unroll
        for (int ks = 0; ks < 2; ks++) {
            const int cc = ccB + 2 * ks;
            uint32_t ah[2][4], al[2][4], bh[2][4], bl[2][4];
            LDSM4(ah[0], sb + OFF_AH + rA[0] * 64 + ((cc ^ swA0) << 4));
            LDSM4(ah[1], sb + OFF_AH + rA[1] * 64 + ((cc ^ swA1) << 4));
            LDSM4(al[0], sb + OFF_AL + rA[0] * 64 + ((cc ^ swA0) << 4));
            LDSM4(al[1], sb + OFF_AL + rA[1] * 64 + ((cc ^ swA1) << 4));
            LDSM4(bh[0], sb + OFF_BH + rB[0] * 64 + ((cc ^ swB0) << 4));
            LDSM4(bh[1], sb + OFF_BH + rB[1] * 64 + ((cc ^ swB1) << 4));
            LDSM4(bl[0], sb + OFF_BL + rB[0] * 64 + ((cc ^ swB0) << 4));
            LDSM4(bl[1], sb + OFF_BL + rB[1] * 64 + ((cc ^ swB1) << 4));
            #pragma unroll
            for (int mi = 0; mi < 2; mi++)
                #pragma unroll
                for (int nf = 0; nf < 4; nf++) {
                    const int p = nf >> 1, s = nf & 1;
                    MMA_BF16(c[mi][nf], ah[mi], bh[p][s], bh[p][s + 2]);
                    MMA_BF16(c[mi][nf], ah[mi], bl[p][s], bl[p][s + 2]);
                    MMA_BF16(c[mi][nf], al[mi], bh[p][s], bh[p][s + 2]);
                }
        }
        if (++st == 3) st = 0;
        __syncthreads();
    }

    // ---- epilogue ----
    #pragma unroll
    for (int mi = 0; mi < 2; mi++) {
        const int r0 = rowBase + wm * 32 + mi * 16 + (lane >> 2);
        #pragma unroll
        for (int nf = 0; nf < 4; nf++) {
            const int col = colBase + wn * 32 + nf * 8 + (lane & 3) * 2;
            if (EPI == 0) {
                if (r0 < M)
                    *(float2*)(Cf + (size_t)r0 * ldc + col) =
                        make_float2(c[mi][nf][0], c[mi][nf][1]);
                if (r0 + 8 < M)
                    *(float2*)(Cf + (size_t)(r0 + 8) * ldc + col) =
                        make_float2(c[mi][nf][2], c[mi][nf][3]);
            } else {
                const float bx = __ldg(bias + col), by = __ldg(bias + col + 1);
                #pragma unroll
                for (int h = 0; h < 2; h++) {
                    const int r = r0 + 8 * h;
                    if (r >= M) continue;
                    float v0 = fmaxf(c[mi][nf][2 * h + 0] + bx, 0.f);
                    float v1 = fmaxf(c[mi][nf][2 * h + 1] + by, 0.f);
                    __nv_bfloat16 h0 = __float2bfloat16(v0);
                    __nv_bfloat16 h1 = __float2bfloat16(v1);
                    size_t o = (size_t)r * ldc + col;
                    *(__nv_bfloat162*)(Chi + o) = __nv_bfloat162(h0, h1);
                    __nv_bfloat16 l0 = __float2bfloat16(v0 - __bfloat162float(h0));
                    __nv_bfloat16 l1 = __float2bfloat16(v1 - __bfloat162float(h1));
                    *(__nv_bfloat162*)(Clo + o) = __nv_bfloat162(l0, l1);
                }
            }
        }
    }
}

// ---------------------------------------------------------------------------
// Gather aggregation (float4 lanes, 4-edge unroll):
//   r = sum_e norm_e * t[src_e] + dinv[i]^2 * t[i] (+ bias) ; (relu)
//   EMIT: write bf16 hi/lo split; else fp32.
// ---------------------------------------------------------------------------
template <int D, bool RELU, bool EMIT, bool BIAS>
__global__ void agg_k(const float* __restrict__ t, float* __restrict__ outf,
                      __nv_bfloat16* __restrict__ ohi, __nv_bfloat16* __restrict__ olo,
                      const float* __restrict__ bias, int n)
{
    constexpr int L = D / 4;        // lanes per node
    constexpr int G = 256 / L;      // nodes per block
    const int lane = threadIdx.x % L;
    const int sub  = threadIdx.x / L;
    const int node = blockIdx.x * G + sub;
    if (node >= n) return;

    float4 b = make_float4(0.f, 0.f, 0.f, 0.f);
    if (BIAS) b = ((const float4*)bias)[lane];
    float di = g_dinv[node];
    float s  = di * di;
    float4 self = __ldg((const float4*)(t + (size_t)node * D) + lane);
    float4 a0 = make_float4(s * self.x + b.x, s * self.y + b.y,
                            s * self.z + b.z, s * self.w + b.w);
    float4 a1 = make_float4(0.f, 0.f, 0.f, 0.f);
    float4 a2 = make_float4(0.f, 0.f, 0.f, 0.f);
    float4 a3 = make_float4(0.f, 0.f, 0.f, 0.f);

    int e   = g_rowptr[node];
    int end = g_rowptr[node + 1];
    for (; e + 3 < end; e += 4) {
        int   s0 = g_csrc[e],   s1 = g_csrc[e + 1];
        int   s2 = g_csrc[e + 2], s3 = g_csrc[e + 3];
        float w0 = g_cnorm[e],  w1 = g_cnorm[e + 1];
        float w2 = g_cnorm[e + 2], w3 = g_cnorm[e + 3];
        float4 v0 = __ldg((const float4*)(t + (size_t)s0 * D) + lane);
        float4 v1 = __ldg((const float4*)(t + (size_t)s1 * D) + lane);
        float4 v2 = __ldg((const float4*)(t + (size_t)s2 * D) + lane);
        float4 v3 = __ldg((const float4*)(t + (size_t)s3 * D) + lane);
        a0.x += w0 * v0.x; a0.y += w0 * v0.y; a0.z += w0 * v0.z; a0.w += w0 * v0.w;
        a1.x += w1 * v1.x; a1.y += w1 * v1.y; a1.z += w1 * v1.z; a1.w += w1 * v1.w;
        a2.x += w2 * v2.x; a2.y += w2 * v2.y; a2.z += w2 * v2.z; a2.w += w2 * v2.w;
        a3.x += w3 * v3.x; a3.y += w3 * v3.y; a3.z += w3 * v3.z; a3.w += w3 * v3.w;
    }
    if (e + 1 < end) {
        int   s0 = g_csrc[e],  s1 = g_csrc[e + 1];
        float w0 = g_cnorm[e], w1 = g_cnorm[e + 1];
        float4 v0 = __ldg((const float4*)(t + (size_t)s0 * D) + lane);
        float4 v1 = __ldg((const float4*)(t + (size_t)s1 * D) + lane);
        a0.x += w0 * v0.x; a0.y += w0 * v0.y; a0.z += w0 * v0.z; a0.w += w0 * v0.w;
        a1.x += w1 * v1.x; a1.y += w1 * v1.y; a1.z += w1 * v1.z; a1.w += w1 * v1.w;
        e += 2;
    }
    if (e < end) {
        float w0 = g_cnorm[e];
        float4 v0 = __ldg((const float4*)(t + (size_t)g_csrc[e] * D) + lane);
        a0.x += w0 * v0.x; a0.y += w0 * v0.y; a0.z += w0 * v0.z; a0.w += w0 * v0.w;
    }
    float4 r = make_float4(a0.x + a1.x + a2.x + a3.x,
                           a0.y + a1.y + a2.y + a3.y,
                           a0.z + a1.z + a2.z + a3.z,
                           a0.w + a1.w + a2.w + a3.w);
    if (RELU) {
        r.x = fmaxf(r.x, 0.f); r.y = fmaxf(r.y, 0.f);
        r.z = fmaxf(r.z, 0.f); r.w = fmaxf(r.w, 0.f);
    }
    if (EMIT) {
        size_t o = (size_t)node * D + lane * 4;
        __nv_bfloat16 h0 = __float2bfloat16(r.x), h1 = __float2bfloat16(r.y);
        __nv_bfloat16 h2 = __float2bfloat16(r.z), h3 = __float2bfloat16(r.w);
        ((__nv_bfloat162*)(ohi + o))[0] = __nv_bfloat162(h0, h1);
        ((__nv_bfloat162*)(ohi + o))[1] = __nv_bfloat162(h2, h3);
        __nv_bfloat16 l0 = __float2bfloat16(r.x - __bfloat162float(h0));
        __nv_bfloat16 l1 = __float2bfloat16(r.y - __bfloat162float(h1));
        __nv_bfloat16 l2 = __float2bfloat16(r.z - __bfloat162float(h2));
        __nv_bfloat16 l3 = __float2bfloat16(r.w - __bfloat162float(h3));
        ((__nv_bfloat162*)(olo + o))[0] = __nv_bfloat162(l0, l1);
        ((__nv_bfloat162*)(olo + o))[1] = __nv_bfloat162(l2, l3);
    } else {
        ((float4*)(outf + (size_t)node * D))[lane] = r;
    }
}

// ---------------------------------------------------------------------------
// Launch
// ---------------------------------------------------------------------------
extern "C" void kernel_launch(void* const* d_in, const int* in_sizes, int n_in,
                              void* d_out, int out_size)
{
    const float* x  = (const float*)d_in[0];
    const int*   ei = (const int*)  d_in[1];
    const float* ew = (const float*)d_in[2];
    const float* W0 = (const float*)d_in[3];
    const float* b0 = (const float*)d_in[4];
    const float* W1 = (const float*)d_in[5];
    const float* b1 = (const float*)d_in[6];
    const float* W2 = (const float*)d_in[7];
    const float* b2 = (const float*)d_in[8];
    float* out = (float*)d_out;

    const int* src = ei;
    const int* dst = ei + EE;

    float *bufA;
    __nv_bfloat16 *hi, *lo, *xhi, *xlo, *w0h, *w0l, *w1h, *w1l, *w2h, *w2l;
    cudaGetSymbolAddress((void**)&bufA, g_bufA);
    cudaGetSymbolAddress((void**)&hi,  g_hi);
    cudaGetSymbolAddress((void**)&lo,  g_lo);
    cudaGetSymbolAddress((void**)&xhi, g_xhi);
    cudaGetSymbolAddress((void**)&xlo, g_xlo);
    cudaGetSymbolAddress((void**)&w0h, g_w0hi); cudaGetSymbolAddress((void**)&w0l, g_w0lo);
    cudaGetSymbolAddress((void**)&w1h, g_w1hi); cudaGetSymbolAddress((void**)&w1l, g_w1lo);
    cudaGetSymbolAddress((void**)&w2h, g_w2hi); cudaGetSymbolAddress((void**)&w2l, g_w2lo);

    const int TB = 256;
    const int gN = (NN + TB - 1) / TB;
    const int gE = (EE + TB - 1) / TB;

    // ---- normalization + coalesced CSR build ----
    k_init<<<gN, TB>>>();
    k_deg_count<<<gE, TB>>>(dst, ew);
    k_blocksum_dinv<<<NBLK, 256>>>();
    k_scanblk<<<1, 512>>>();
    k_rowptr<<<NBLK, 256>>>();
    k_fill<<<gE, TB>>>(src, dst, ew);

    // ---- weight prep: transpose + split (single fused launch) ----
    const int WTOT = F_IN * HID + HID * HID + HID * NC;
    k_wsplit_all<<<(WTOT + 255) / 256, 256>>>(W0, W1, W2);

    const int gridM = (NN + 127) / 128;   // 782
    constexpr int SMEM3 = 3 * 24576;      // 73728 B dynamic
    cudaFuncSetAttribute((const void*)gemm_mma<0>,
                         cudaFuncAttributeMaxDynamicSharedMemorySize, SMEM3);
    cudaFuncSetAttribute((const void*)gemm_mma<1>,
                         cudaFuncAttributeMaxDynamicSharedMemorySize, SMEM3);

    // ---- Layer 0:  h0 = relu(agg(x) @ W0 + b0)   [agg first: 128-dim gathers]
    agg_k<F_IN, false, true, false><<<(NN + 7) / 8, 256>>>(
        x, nullptr, xhi, xlo, nullptr, NN);
    gemm_mma<1><<<dim3(HID / 64, gridM), 256, SMEM3>>>(
        NN, F_IN, xhi, xlo, w0h, w0l, nullptr, hi, lo, b0, HID);

    // ---- Layer 1:  h1 = relu(agg(h0 @ W1) + b1)
    gemm_mma<0><<<dim3(HID / 64, gridM), 256, SMEM3>>>(
        NN, HID, hi, lo, w1h, w1l, bufA, nullptr, nullptr, nullptr, HID);
    agg_k<HID, true, true, true><<<(NN + 3) / 4, 256>>>(
        bufA, nullptr, hi, lo, b1, NN);

    // ---- Layer 2:  out = agg(h1 @ W2) + b2   [64-dim gathers]
    gemm_mma<0><<<dim3(NC / 64, gridM), 256, SMEM3>>>(
        NN, HID, hi, lo, w2h, w2l, bufA, nullptr, nullptr, nullptr, NC);
    agg_k<NC, false, false, true><<<(NN + 15) / 16, 256>>>(
        bufA, out, nullptr, nullptr, b2, NN);
}

// round 12
// speedup vs baseline: 1.1540x; 1.1540x over previous
#include <cuda_runtime.h>
#include <cuda_bf16.h>
#include <cstdint>
#include <math.h>

// Problem constants (fixed by the dataset)
#define NN   100000
#define EE   1600000
#define F_IN 128
#define HID  256
#define NC   64
#define NBLK ((NN + 255) / 256)   // 391

// ---------------------------------------------------------------------------
// Scratch (static __device__ arrays — no allocation allowed)
// ---------------------------------------------------------------------------
__device__ float g_deg[NN];
__device__ float g_dinv[NN];
__device__ int   g_wptr[NN];
__device__ int   g_rowptr[NN + 1];
__device__ int   g_blksum[NBLK];
__device__ int   g_blkoff[NBLK];
__device__ int   g_csrc[EE];
__device__ float g_cnorm[EE];
__device__ __align__(16) float         g_bufA[(size_t)NN * HID];   // GEMM fp32 out
__device__ __align__(16) __nv_bfloat16 g_hi[(size_t)NN * HID];     // activations hi
__device__ __align__(16) __nv_bfloat16 g_lo[(size_t)NN * HID];     // activations lo
__device__ __align__(16) __nv_bfloat16 g_xhi[(size_t)NN * F_IN];   // agg(x) hi
__device__ __align__(16) __nv_bfloat16 g_xlo[(size_t)NN * F_IN];   // agg(x) lo
__device__ __align__(16) __nv_bfloat16 g_w0hi[HID * F_IN], g_w0lo[HID * F_IN];
__device__ __align__(16) __nv_bfloat16 g_w1hi[HID * HID],  g_w1lo[HID * HID];
__device__ __align__(16) __nv_bfloat16 g_w2hi[NC * HID],   g_w2lo[NC * HID];

// ---------------------------------------------------------------------------
// PTX helpers (portable sm_80+; works on generic sm_103 target)
// ---------------------------------------------------------------------------
__device__ __forceinline__ uint32_t smem_u32(const void* p) {
    uint32_t a;
    asm("{ .reg .u64 t; cvta.to.shared.u64 t, %1; cvt.u32.u64 %0, t; }"
        : "=r"(a) : "l"(p));
    return a;
}

#define LDSM4(r, addr) \
    asm volatile("ldmatrix.sync.aligned.m8n8.x4.shared.b16 {%0,%1,%2,%3}, [%4];" \
        : "=r"((r)[0]), "=r"((r)[1]), "=r"((r)[2]), "=r"((r)[3]) : "r"(addr))

#define MMA_BF16(c, a, b0, b1) \
    asm volatile("mma.sync.aligned.m16n8k16.row.col.f32.bf16.bf16.f32 " \
        "{%0,%1,%2,%3}, {%4,%5,%6,%7}, {%8,%9}, {%0,%1,%2,%3};" \
        : "+f"((c)[0]), "+f"((c)[1]), "+f"((c)[2]), "+f"((c)[3]) \
        : "r"((a)[0]), "r"((a)[1]), "r"((a)[2]), "r"((a)[3]), "r"(b0), "r"(b1))

#define CP16(dst, src, sz) \
    asm volatile("cp.async.cg.shared.global [%0], [%1], 16, %2;" \
        :: "r"(dst), "l"(src), "r"(sz) : "memory")
#define CP_COMMIT() asm volatile("cp.async.commit_group;" ::: "memory")
template <int N>
__device__ __forceinline__ void cp_wait() {
    asm volatile("cp.async.wait_group %0;" :: "n"(N) : "memory");
}

// ---------------------------------------------------------------------------
// Preprocessing kernels
// ---------------------------------------------------------------------------
__global__ void k_init()
{
    int i = blockIdx.x * blockDim.x + threadIdx.x;
    if (i < NN) { g_deg[i] = 1.0f; g_wptr[i] = 0; }
}

__global__ void k_deg_count(const int* __restrict__ dst, const float* __restrict__ w)
{
    int e = blockIdx.x * blockDim.x + threadIdx.x;
    if (e < EE) {
        int d = dst[e];
        atomicAdd(&g_deg[d], w[e]);
        atomicAdd(&g_wptr[d], 1);
    }
}

// blocksum of counts + dinv (fused: same index space)
__global__ void k_blocksum_dinv()
{
    __shared__ int sh[256];
    int i = blockIdx.x * 256 + threadIdx.x;
    sh[threadIdx.x] = (i < NN) ? g_wptr[i] : 0;
    if (i < NN) g_dinv[i] = rsqrtf(g_deg[i]);
    __syncthreads();
    for (int o = 128; o > 0; o >>= 1) {
        if (threadIdx.x < o) sh[threadIdx.x] += sh[threadIdx.x + o];
        __syncthreads();
    }
    if (threadIdx.x == 0) g_blksum[blockIdx.x] = sh[0];
}

__global__ void k_scanblk()
{
    __shared__ int sh[512];
    int t = threadIdx.x;
    int v = (t < NBLK) ? g_blksum[t] : 0;
    sh[t] = v;
    __syncthreads();
    for (int o = 1; o < 512; o <<= 1) {
        int a = (t >= o) ? sh[t - o] : 0;
        __syncthreads();
        sh[t] += a;
        __syncthreads();
    }
    if (t < NBLK) g_blkoff[t] = sh[t] - v;   // exclusive
}

__global__ void k_rowptr()
{
    __shared__ int sh[256];
    int i = blockIdx.x * 256 + threadIdx.x;
    int v = (i < NN) ? g_wptr[i] : 0;
    sh[threadIdx.x] = v;
    __syncthreads();
    for (int o = 1; o < 256; o <<= 1) {
        int a = (threadIdx.x >= o) ? sh[threadIdx.x - o] : 0;
        __syncthreads();
        sh[threadIdx.x] += a;
        __syncthreads();
    }
    if (i < NN) {
        int off = g_blkoff[blockIdx.x] + sh[threadIdx.x] - v;
        g_rowptr[i] = off;
        g_wptr[i]   = off;   // write cursor for fill
    }
    if (i == NN - 1) g_rowptr[NN] = EE;
}

__global__ void k_fill(const int* __restrict__ src, const int* __restrict__ dst,
                       const float* __restrict__ w)
{
    int e = blockIdx.x * blockDim.x + threadIdx.x;
    if (e < EE) {
        int s = src[e], d = dst[e];
        float nm = g_dinv[s] * w[e] * g_dinv[d];
        int slot = atomicAdd(&g_wptr[d], 1);
        g_csrc[slot]  = s;
        g_cnorm[slot] = nm;
    }
}

// All three weights: W[K,N] row-major -> Wt[N,K] K-major, split hi/lo (fused)
__global__ void k_wsplit_all(const float* __restrict__ W0,
                             const float* __restrict__ W1,
                             const float* __restrict__ W2)
{
    int i = blockIdx.x * blockDim.x + threadIdx.x;
    const float* W; __nv_bfloat16 *thi, *tlo; int K, Ncols, j;
    if (i < F_IN * HID)                   { W = W0; thi = g_w0hi; tlo = g_w0lo; K = F_IN; Ncols = HID; j = i; }
    else if (i < F_IN * HID + HID * HID)  { W = W1; thi = g_w1hi; tlo = g_w1lo; K = HID;  Ncols = HID; j = i - F_IN * HID; }
    else if (i < F_IN * HID + HID * HID + HID * NC)
                                          { W = W2; thi = g_w2hi; tlo = g_w2lo; K = HID;  Ncols = NC;  j = i - F_IN * HID - HID * HID; }
    else return;
    int n = j / K, k = j % K;
    float v = W[k * Ncols + n];
    __nv_bfloat16 h = __float2bfloat16(v);
    thi[j] = h;
    tlo[j] = __float2bfloat16(v - __bfloat162float(h));
}

// ---------------------------------------------------------------------------
// HMMA split-bf16 GEMM, cp.async double-buffered (round-10 proven config).
//   C[M, ldc] = A[M, KT] @ Bt[Ncols, KT]^T ; 3 terms Ah*Bh + Ah*Bl + Al*Bh.
//   BM=128, BN=64, BK=32, 256 threads (warps 4m x 2n, warp tile 32x32).
//   Smem: 2 stages x 24576 B (static 48 KB), 64 B rows, XOR-16B swizzle.
//   EPI=0: fp32 store. EPI=1: bias+relu+hi/lo bf16.
// ---------------------------------------------------------------------------
template <int EPI>
__global__ void __launch_bounds__(256)
gemm_mma(int M, int KT,
         const __nv_bfloat16* __restrict__ Ahi, const __nv_bfloat16* __restrict__ Alo,
         const __nv_bfloat16* __restrict__ Bhi, const __nv_bfloat16* __restrict__ Blo,
         float* __restrict__ Cf,
         __nv_bfloat16* __restrict__ Chi, __nv_bfloat16* __restrict__ Clo,
         const float* __restrict__ bias, int ldc)
{
    constexpr int STG = 24576;          // (128*2 + 64*2) rows * 64 B
    constexpr int OFF_AH = 0, OFF_AL = 8192, OFF_BH = 16384, OFF_BL = 20480;

    __shared__ __align__(16) char sm[2 * STG];
    const uint32_t smb = smem_u32(sm);

    const int tid  = threadIdx.x;
    const int lane = tid & 31, wid = tid >> 5;
    const int wm = wid & 3;             // 0..3  (m)
    const int wn = wid >> 2;            // 0..1  (n)
    const int rowBase = blockIdx.y * 128;
    const int colBase = blockIdx.x * 64;

    float c[2][4][4];
    #pragma unroll
    for (int mi = 0; mi < 2; mi++)
        #pragma unroll
        for (int nf = 0; nf < 4; nf++)
            #pragma unroll
            for (int j = 0; j < 4; j++) c[mi][nf][j] = 0.f;

    // ldmatrix per-lane rows + swizzle keys
    const int lane15 = lane & 15;
    int  rA[2], rB[2];
    rA[0] = wm * 32 + lane15;  rA[1] = rA[0] + 16;
    rB[0] = wn * 32 + lane15;  rB[1] = rB[0] + 16;
    const int swA0 = (rA[0] >> 1) & 3, swA1 = (rA[1] >> 1) & 3;
    const int swB0 = (rB[0] >> 1) & 3, swB1 = (rB[1] >> 1) & 3;
    const int ccB  = lane >> 4;

    const int nchunk = KT >> 5;

    // ---- tile loader (cp.async) ----
    auto ld_tiles = [&](int st, int ch) {
        const uint32_t sb = smb + st * STG;
        const int k0 = ch * 32;
        #pragma unroll
        for (int i = tid; i < 512; i += 256) {      // A: 128 rows x 4 chunks
            int row = i >> 2, cc = i & 3;
            int gr  = rowBase + row;
            uint32_t sz = (gr < M) ? 16u : 0u;
            int gra = (gr < M) ? gr : (M - 1);
            size_t go = (size_t)gra * KT + k0 + cc * 8;
            uint32_t d = row * 64 + (((cc ^ ((row >> 1) & 3))) << 4);
            CP16(sb + OFF_AH + d, (const char*)(Ahi + go), sz);
            CP16(sb + OFF_AL + d, (const char*)(Alo + go), sz);
        }
        {                                            // B: 64 rows x 4 chunks
            int row = tid >> 2, cc = tid & 3;
            size_t go = (size_t)(colBase + row) * KT + k0 + cc * 8;
            uint32_t d = row * 64 + (((cc ^ ((row >> 1) & 3))) << 4);
            CP16(sb + OFF_BH + d, (const char*)(Bhi + go), 16u);
            CP16(sb + OFF_BL + d, (const char*)(Blo + go), 16u);
        }
    };

    ld_tiles(0, 0);
    CP_COMMIT();

    for (int ch = 0; ch < nchunk; ch++) {
        if (ch + 1 < nchunk) { ld_tiles((ch + 1) & 1, ch + 1); CP_COMMIT(); }
        if (ch + 1 < nchunk) cp_wait<1>(); else cp_wait<0>();
        __syncthreads();

        const uint32_t sb = smb + (ch & 1) * STG;
        #pragma unroll
        for (int ks = 0; ks < 2; ks++) {
            const int cc = ccB + 2 * ks;
            uint32_t ah[2][4], al[2][4], bh[2][4], bl[2][4];
            LDSM4(ah[0], sb + OFF_AH + rA[0] * 64 + ((cc ^ swA0) << 4));
            LDSM4(ah[1], sb + OFF_AH + rA[1] * 64 + ((cc ^ swA1) << 4));
            LDSM4(al[0], sb + OFF_AL + rA[0] * 64 + ((cc ^ swA0) << 4));
            LDSM4(al[1], sb + OFF_AL + rA[1] * 64 + ((cc ^ swA1) << 4));
            LDSM4(bh[0], sb + OFF_BH + rB[0] * 64 + ((cc ^ swB0) << 4));
            LDSM4(bh[1], sb + OFF_BH + rB[1] * 64 + ((cc ^ swB1) << 4));
            LDSM4(bl[0], sb + OFF_BL + rB[0] * 64 + ((cc ^ swB0) << 4));
            LDSM4(bl[1], sb + OFF_BL + rB[1] * 64 + ((cc ^ swB1) << 4));
            #pragma unroll
            for (int mi = 0; mi < 2; mi++)
                #pragma unroll
                for (int nf = 0; nf < 4; nf++) {
                    const int p = nf >> 1, s = nf & 1;
                    MMA_BF16(c[mi][nf], ah[mi], bh[p][s], bh[p][s + 2]);
                    MMA_BF16(c[mi][nf], ah[mi], bl[p][s], bl[p][s + 2]);
                    MMA_BF16(c[mi][nf], al[mi], bh[p][s], bh[p][s + 2]);
                }
        }
        __syncthreads();
    }

    // ---- epilogue ----
    #pragma unroll
    for (int mi = 0; mi < 2; mi++) {
        const int r0 = rowBase + wm * 32 + mi * 16 + (lane >> 2);
        #pragma unroll
        for (int nf = 0; nf < 4; nf++) {
            const int col = colBase + wn * 32 + nf * 8 + (lane & 3) * 2;
            if (EPI == 0) {
                if (r0 < M)
                    *(float2*)(Cf + (size_t)r0 * ldc + col) =
                        make_float2(c[mi][nf][0], c[mi][nf][1]);
                if (r0 + 8 < M)
                    *(float2*)(Cf + (size_t)(r0 + 8) * ldc + col) =
                        make_float2(c[mi][nf][2], c[mi][nf][3]);
            } else {
                const float bx = __ldg(bias + col), by = __ldg(bias + col + 1);
                #pragma unroll
                for (int h = 0; h < 2; h++) {
                    const int r = r0 + 8 * h;
                    if (r >= M) continue;
                    float v0 = fmaxf(c[mi][nf][2 * h + 0] + bx, 0.f);
                    float v1 = fmaxf(c[mi][nf][2 * h + 1] + by, 0.f);
                    __nv_bfloat16 h0 = __float2bfloat16(v0);
                    __nv_bfloat16 h1 = __float2bfloat16(v1);
                    size_t o = (size_t)r * ldc + col;
                    *(__nv_bfloat162*)(Chi + o) = __nv_bfloat162(h0, h1);
                    __nv_bfloat16 l0 = __float2bfloat16(v0 - __bfloat162float(h0));
                    __nv_bfloat16 l1 = __float2bfloat16(v1 - __bfloat162float(h1));
                    *(__nv_bfloat162*)(Clo + o) = __nv_bfloat162(l0, l1);
                }
            }
        }
    }
}

// ---------------------------------------------------------------------------
// Gather aggregation (float4 lanes, 2-edge unroll — round-10 proven config):
//   r = sum_e norm_e * t[src_e] + dinv[i]^2 * t[i] (+ bias) ; (relu)
//   EMIT: write bf16 hi/lo split; else fp32.
// ---------------------------------------------------------------------------
template <int D, bool RELU, bool EMIT, bool BIAS>
__global__ void agg_k(const float* __restrict__ t, float* __restrict__ outf,
                      __nv_bfloat16* __restrict__ ohi, __nv_bfloat16* __restrict__ olo,
                      const float* __restrict__ bias, int n)
{
    constexpr int L = D / 4;        // lanes per node
    constexpr int G = 256 / L;      // nodes per block
    const int lane = threadIdx.x % L;
    const int sub  = threadIdx.x / L;
    const int node = blockIdx.x * G + sub;
    if (node >= n) return;

    float4 b = make_float4(0.f, 0.f, 0.f, 0.f);
    if (BIAS) b = ((const float4*)bias)[lane];
    float di = g_dinv[node];
    float s  = di * di;
    float4 self = __ldg((const float4*)(t + (size_t)node * D) + lane);
    float4 a0 = make_float4(s * self.x + b.x, s * self.y + b.y,
                            s * self.z + b.z, s * self.w + b.w);
    float4 a1 = make_float4(0.f, 0.f, 0.f, 0.f);

    int e   = g_rowptr[node];
    int end = g_rowptr[node + 1];
    for (; e + 1 < end; e += 2) {
        int   s0 = g_csrc[e],  s1 = g_csrc[e + 1];
        float w0 = g_cnorm[e], w1 = g_cnorm[e + 1];
        float4 v0 = __ldg((const float4*)(t + (size_t)s0 * D) + lane);
        float4 v1 = __ldg((const float4*)(t + (size_t)s1 * D) + lane);
        a0.x += w0 * v0.x; a0.y += w0 * v0.y; a0.z += w0 * v0.z; a0.w += w0 * v0.w;
        a1.x += w1 * v1.x; a1.y += w1 * v1.y; a1.z += w1 * v1.z; a1.w += w1 * v1.w;
    }
    if (e < end) {
        float w0 = g_cnorm[e];
        float4 v0 = __ldg((const float4*)(t + (size_t)g_csrc[e] * D) + lane);
        a0.x += w0 * v0.x; a0.y += w0 * v0.y; a0.z += w0 * v0.z; a0.w += w0 * v0.w;
    }
    float4 r = make_float4(a0.x + a1.x, a0.y + a1.y, a0.z + a1.z, a0.w + a1.w);
    if (RELU) {
        r.x = fmaxf(r.x, 0.f); r.y = fmaxf(r.y, 0.f);
        r.z = fmaxf(r.z, 0.f); r.w = fmaxf(r.w, 0.f);
    }
    if (EMIT) {
        size_t o = (size_t)node * D + lane * 4;
        __nv_bfloat16 h0 = __float2bfloat16(r.x), h1 = __float2bfloat16(r.y);
        __nv_bfloat16 h2 = __float2bfloat16(r.z), h3 = __float2bfloat16(r.w);
        ((__nv_bfloat162*)(ohi + o))[0] = __nv_bfloat162(h0, h1);
        ((__nv_bfloat162*)(ohi + o))[1] = __nv_bfloat162(h2, h3);
        __nv_bfloat16 l0 = __float2bfloat16(r.x - __bfloat162float(h0));
        __nv_bfloat16 l1 = __float2bfloat16(r.y - __bfloat162float(h1));
        __nv_bfloat16 l2 = __float2bfloat16(r.z - __bfloat162float(h2));
        __nv_bfloat16 l3 = __float2bfloat16(r.w - __bfloat162float(h3));
        ((__nv_bfloat162*)(olo + o))[0] = __nv_bfloat162(l0, l1);
        ((__nv_bfloat162*)(olo + o))[1] = __nv_bfloat162(l2, l3);
    } else {
        ((float4*)(outf + (size_t)node * D))[lane] = r;
    }
}

// ---------------------------------------------------------------------------
// Launch
// ---------------------------------------------------------------------------
extern "C" void kernel_launch(void* const* d_in, const int* in_sizes, int n_in,
                              void* d_out, int out_size)
{
    const float* x  = (const float*)d_in[0];
    const int*   ei = (const int*)  d_in[1];
    const float* ew = (const float*)d_in[2];
    const float* W0 = (const float*)d_in[3];
    const float* b0 = (const float*)d_in[4];
    const float* W1 = (const float*)d_in[5];
    const float* b1 = (const float*)d_in[6];
    const float* W2 = (const float*)d_in[7];
    const float* b2 = (const float*)d_in[8];
    float* out = (float*)d_out;

    const int* src = ei;
    const int* dst = ei + EE;

    float *bufA;
    __nv_bfloat16 *hi, *lo, *xhi, *xlo, *w0h, *w0l, *w1h, *w1l, *w2h, *w2l;
    cudaGetSymbolAddress((void**)&bufA, g_bufA);
    cudaGetSymbolAddress((void**)&hi,  g_hi);
    cudaGetSymbolAddress((void**)&lo,  g_lo);
    cudaGetSymbolAddress((void**)&xhi, g_xhi);
    cudaGetSymbolAddress((void**)&xlo, g_xlo);
    cudaGetSymbolAddress((void**)&w0h, g_w0hi); cudaGetSymbolAddress((void**)&w0l, g_w0lo);
    cudaGetSymbolAddress((void**)&w1h, g_w1hi); cudaGetSymbolAddress((void**)&w1l, g_w1lo);
    cudaGetSymbolAddress((void**)&w2h, g_w2hi); cudaGetSymbolAddress((void**)&w2l, g_w2lo);

    const int TB = 256;
    const int gN = (NN + TB - 1) / TB;
    const int gE = (EE + TB - 1) / TB;

    // ---- normalization + coalesced CSR build ----
    k_init<<<gN, TB>>>();
    k_deg_count<<<gE, TB>>>(dst, ew);
    k_blocksum_dinv<<<NBLK, 256>>>();
    k_scanblk<<<1, 512>>>();
    k_rowptr<<<NBLK, 256>>>();
    k_fill<<<gE, TB>>>(src, dst, ew);

    // ---- weight prep: transpose + split (single fused launch) ----
    const int WTOT = F_IN * HID + HID * HID + HID * NC;
    k_wsplit_all<<<(WTOT + 255) / 256, 256>>>(W0, W1, W2);

    const int gridM = (NN + 127) / 128;   // 782

    // ---- Layer 0:  h0 = relu(agg(x) @ W0 + b0)   [agg first: 128-dim gathers]
    agg_k<F_IN, false, true, false><<<(NN + 7) / 8, 256>>>(
        x, nullptr, xhi, xlo, nullptr, NN);
    gemm_mma<1><<<dim3(HID / 64, gridM), 256>>>(
        NN, F_IN, xhi, xlo, w0h, w0l, nullptr, hi, lo, b0, HID);

    // ---- Layer 1:  h1 = relu(agg(h0 @ W1) + b1)
    gemm_mma<0><<<dim3(HID / 64, gridM), 256>>>(
        NN, HID, hi, lo, w1h, w1l, bufA, nullptr, nullptr, nullptr, HID);
    agg_k<HID, true, true, true><<<(NN + 3) / 4, 256>>>(
        bufA, nullptr, hi, lo, b1, NN);

    // ---- Layer 2:  out = agg(h1 @ W2) + b2   [64-dim gathers]
    gemm_mma<0><<<dim3(NC / 64, gridM), 256>>>(
        NN, HID, hi, lo, w2h, w2l, bufA, nullptr, nullptr, nullptr, NC);
    agg_k<NC, false, false, true><<<(NN + 15) / 16, 256>>>(
        bufA, out, nullptr, nullptr, b2, NN);
}

// round 13
// speedup vs baseline: 1.3136x; 1.1383x over previous
#include <cuda_runtime.h>
#include <cuda_bf16.h>
#include <cstdint>
#include <math.h>

// Problem constants (fixed by the dataset)
#define NN   100000
#define EE   1600000
#define F_IN 128
#define HID  256
#define NC   64
#define NBLK ((NN + 255) / 256)   // 391

// ---------------------------------------------------------------------------
// Scratch (static __device__ arrays — no allocation allowed)
// ---------------------------------------------------------------------------
__device__ float g_deg[NN];
__device__ float g_dinv[NN];
__device__ int   g_wptr[NN];
__device__ int   g_rowptr[NN + 1];
__device__ int   g_blksum[NBLK];
__device__ int   g_blkoff[NBLK];
__device__ int   g_csrc[EE];
__device__ float g_cnorm[EE];
__device__ __align__(16) float g_bufA[(size_t)NN * HID];   // GEMM fp32 outputs
__device__ __align__(16) float g_bufB[(size_t)NN * HID];   // GEMM tf32 inputs
__device__ __align__(16) float g_xagg[(size_t)NN * F_IN];  // agg(x), tf32-rounded
__device__ __align__(16) float g_w0t[HID * F_IN];          // W0^T, tf32-rounded
__device__ __align__(16) float g_w1t[HID * HID];
__device__ __align__(16) float g_w2t[NC * HID];

// ---------------------------------------------------------------------------
// PTX helpers (portable sm_80+; works on generic sm_103 target)
// ---------------------------------------------------------------------------
__device__ __forceinline__ uint32_t smem_u32(const void* p) {
    uint32_t a;
    asm("{ .reg .u64 t; cvta.to.shared.u64 t, %1; cvt.u32.u64 %0, t; }"
        : "=r"(a) : "l"(p));
    return a;
}

__device__ __forceinline__ float tf32r(float v) {
    uint32_t o;
    asm("cvt.rna.tf32.f32 %0, %1;" : "=r"(o) : "f"(v));
    return __uint_as_float(o);
}

#define LDSM4(r, addr) \
    asm volatile("ldmatrix.sync.aligned.m8n8.x4.shared.b16 {%0,%1,%2,%3}, [%4];" \
        : "=r"((r)[0]), "=r"((r)[1]), "=r"((r)[2]), "=r"((r)[3]) : "r"(addr))

#define MMA_TF32(c, a, b0, b1) \
    asm volatile("mma.sync.aligned.m16n8k8.row.col.f32.tf32.tf32.f32 " \
        "{%0,%1,%2,%3}, {%4,%5,%6,%7}, {%8,%9}, {%0,%1,%2,%3};" \
        : "+f"((c)[0]), "+f"((c)[1]), "+f"((c)[2]), "+f"((c)[3]) \
        : "r"((a)[0]), "r"((a)[1]), "r"((a)[2]), "r"((a)[3]), "r"(b0), "r"(b1))

#define CP16(dst, src, sz) \
    asm volatile("cp.async.cg.shared.global [%0], [%1], 16, %2;" \
        :: "r"(dst), "l"(src), "r"(sz) : "memory")
#define CP_COMMIT() asm volatile("cp.async.commit_group;" ::: "memory")
template <int N>
__device__ __forceinline__ void cp_wait() {
    asm volatile("cp.async.wait_group %0;" :: "n"(N) : "memory");
}

// ---------------------------------------------------------------------------
// Preprocessing kernels
// ---------------------------------------------------------------------------
__global__ void k_init()
{
    int i = blockIdx.x * blockDim.x + threadIdx.x;
    if (i < NN) { g_deg[i] = 1.0f; g_wptr[i] = 0; }
}

__global__ void k_deg_count(const int* __restrict__ dst, const float* __restrict__ w)
{
    int e = blockIdx.x * blockDim.x + threadIdx.x;
    if (e < EE) {
        int d = dst[e];
        atomicAdd(&g_deg[d], w[e]);
        atomicAdd(&g_wptr[d], 1);
    }
}

// blocksum of counts + dinv (fused: same index space)
__global__ void k_blocksum_dinv()
{
    __shared__ int sh[256];
    int i = blockIdx.x * 256 + threadIdx.x;
    sh[threadIdx.x] = (i < NN) ? g_wptr[i] : 0;
    if (i < NN) g_dinv[i] = rsqrtf(g_deg[i]);
    __syncthreads();
    for (int o = 128; o > 0; o >>= 1) {
        if (threadIdx.x < o) sh[threadIdx.x] += sh[threadIdx.x + o];
        __syncthreads();
    }
    if (threadIdx.x == 0) g_blksum[blockIdx.x] = sh[0];
}

__global__ void k_scanblk()
{
    __shared__ int sh[512];
    int t = threadIdx.x;
    int v = (t < NBLK) ? g_blksum[t] : 0;
    sh[t] = v;
    __syncthreads();
    for (int o = 1; o < 512; o <<= 1) {
        int a = (t >= o) ? sh[t - o] : 0;
        __syncthreads();
        sh[t] += a;
        __syncthreads();
    }
    if (t < NBLK) g_blkoff[t] = sh[t] - v;   // exclusive
}

__global__ void k_rowptr()
{
    __shared__ int sh[256];
    int i = blockIdx.x * 256 + threadIdx.x;
    int v = (i < NN) ? g_wptr[i] : 0;
    sh[threadIdx.x] = v;
    __syncthreads();
    for (int o = 1; o < 256; o <<= 1) {
        int a = (threadIdx.x >= o) ? sh[threadIdx.x - o] : 0;
        __syncthreads();
        sh[threadIdx.x] += a;
        __syncthreads();
    }
    if (i < NN) {
        int off = g_blkoff[blockIdx.x] + sh[threadIdx.x] - v;
        g_rowptr[i] = off;
        g_wptr[i]   = off;   // write cursor for fill
    }
    if (i == NN - 1) g_rowptr[NN] = EE;
}

__global__ void k_fill(const int* __restrict__ src, const int* __restrict__ dst,
                       const float* __restrict__ w)
{
    int e = blockIdx.x * blockDim.x + threadIdx.x;
    if (e < EE) {
        int s = src[e], d = dst[e];
        float nm = g_dinv[s] * w[e] * g_dinv[d];
        int slot = atomicAdd(&g_wptr[d], 1);
        g_csrc[slot]  = s;
        g_cnorm[slot] = nm;
    }
}

// All three weights: W[K,N] row-major -> Wt[N,K] K-major fp32, tf32-rounded
__global__ void k_wsplit_all(const float* __restrict__ W0,
                             const float* __restrict__ W1,
                             const float* __restrict__ W2)
{
    int i = blockIdx.x * blockDim.x + threadIdx.x;
    const float* W; float* wt; int K, Ncols, j;
    if (i < F_IN * HID)                   { W = W0; wt = g_w0t; K = F_IN; Ncols = HID; j = i; }
    else if (i < F_IN * HID + HID * HID)  { W = W1; wt = g_w1t; K = HID;  Ncols = HID; j = i - F_IN * HID; }
    else if (i < F_IN * HID + HID * HID + HID * NC)
                                          { W = W2; wt = g_w2t; K = HID;  Ncols = NC;  j = i - F_IN * HID - HID * HID; }
    else return;
    int n = j / K, k = j % K;
    wt[j] = tf32r(W[k * Ncols + n]);
}

// ---------------------------------------------------------------------------
// TF32 HMMA GEMM, cp.async double-buffered (round-12 proven structure).
//   C[M, ldc] = A[M, KT] @ Bt[Ncols, KT]^T ; A,Bt fp32 pre-rounded to tf32.
//   BM=128, BN=64, BK=32, 256 threads (warps 4m x 2n, warp tile 32x32).
//   Smem: 2 stages x 24576 B (static 48 KB), 128 B rows, XOR-16B swizzle.
//   EPI=0: plain fp32 store. EPI=1: bias+relu+tf32 round.
// ---------------------------------------------------------------------------
template <int EPI>
__global__ void __launch_bounds__(256)
gemm_tf32(int M, int KT,
          const float* __restrict__ A, const float* __restrict__ B,
          float* __restrict__ Cf, const float* __restrict__ bias, int ldc)
{
    constexpr int STG = 24576;          // A 128*128B + B 64*128B
    constexpr int OFF_A = 0, OFF_B = 16384;

    __shared__ __align__(16) char sm[2 * STG];
    const uint32_t smb = smem_u32(sm);

    const int tid  = threadIdx.x;
    const int lane = tid & 31, wid = tid >> 5;
    const int wm = wid & 3;             // 0..3  (m)
    const int wn = wid >> 2;            // 0..1  (n)
    const int rowBase = blockIdx.y * 128;
    const int colBase = blockIdx.x * 64;

    float c[2][4][4];
    #pragma unroll
    for (int mi = 0; mi < 2; mi++)
        #pragma unroll
        for (int nf = 0; nf < 4; nf++)
            #pragma unroll
            for (int j = 0; j < 4; j++) c[mi][nf][j] = 0.f;

    // ldmatrix lane addressing:
    // A x4 quadrants: [rows r..r+7, c16+0], [rows+8, c16+0], [rows, c16+1], [rows+8, c16+1]
    const int rr = lane & 7;
    const int qA = lane >> 3;
    const int cA = qA >> 1;                               // +0 / +1 (16B units)
    const int rA0 = wm * 32 + ((qA & 1) << 3) + rr;       // mi=0
    const int rA1 = rA0 + 16;                             // mi=1
    const uint32_t aOff0 = OFF_A + rA0 * 128; const int aX0 = rA0 & 7;
    const uint32_t aOff1 = OFF_A + rA1 * 128; const int aX1 = rA1 & 7;
    // B x4 quadrants: [n r..r+7, c+0], [n r..r+7, c+1], [n r+8.., c+0], [n r+8.., c+1]
    const int cB = (lane >> 3) & 1;
    const int rB0 = wn * 32 + ((lane >> 4) << 3) + rr;    // p=0 (n groups 0,1)
    const int rB1 = rB0 + 16;                             // p=1 (n groups 2,3)
    const uint32_t bOff0 = OFF_B + rB0 * 128; const int bX0 = rB0 & 7;
    const uint32_t bOff1 = OFF_B + rB1 * 128; const int bX1 = rB1 & 7;

    const int nchunk = KT >> 5;

    // ---- tile loader (cp.async): rows of 32 fp32 = 8 x 16B chunks, swizzled
    auto ld_tiles = [&](int st, int ch) {
        const uint32_t sb = smb + st * STG;
        const int k0 = ch * 32;
        #pragma unroll
        for (int i = tid; i < 1024; i += 256) {     // A: 128 rows x 8 chunks
            int row = i >> 3, cc = i & 7;
            int gr  = rowBase + row;
            uint32_t sz = (gr < M) ? 16u : 0u;
            int gra = (gr < M) ? gr : (M - 1);
            size_t go = (size_t)gra * KT + k0 + cc * 4;
            uint32_t d = row * 128 + ((cc ^ (row & 7)) << 4);
            CP16(sb + OFF_A + d, (const char*)(A + go), sz);
        }
        #pragma unroll
        for (int i = tid; i < 512; i += 256) {      // B: 64 rows x 8 chunks
            int row = i >> 3, cc = i & 7;
            size_t go = (size_t)(colBase + row) * KT + k0 + cc * 4;
            uint32_t d = row * 128 + ((cc ^ (row & 7)) << 4);
            CP16(sb + OFF_B + d, (const char*)(B + go), 16u);
        }
    };

    ld_tiles(0, 0);
    CP_COMMIT();

    for (int ch = 0; ch < nchunk; ch++) {
        if (ch + 1 < nchunk) { ld_tiles((ch + 1) & 1, ch + 1); CP_COMMIT(); }
        if (ch + 1 < nchunk) cp_wait<1>(); else cp_wait<0>();
        __syncthreads();

        const uint32_t sb = smb + (ch & 1) * STG;
        #pragma unroll
        for (int ks = 0; ks < 4; ks++) {
            uint32_t a[2][4], b[2][4];
            LDSM4(a[0], sb + aOff0 + (((2 * ks + cA) ^ aX0) << 4));
            LDSM4(a[1], sb + aOff1 + (((2 * ks + cA) ^ aX1) << 4));
            LDSM4(b[0], sb + bOff0 + (((2 * ks + cB) ^ bX0) << 4));
            LDSM4(b[1], sb + bOff1 + (((2 * ks + cB) ^ bX1) << 4));
            #pragma unroll
            for (int mi = 0; mi < 2; mi++)
                #pragma unroll
                for (int g = 0; g < 4; g++) {
                    const int p = g >> 1, s = (g & 1) * 2;
                    MMA_TF32(c[mi][g], a[mi], b[p][s], b[p][s + 1]);
                }
        }
        __syncthreads();
    }

    // ---- epilogue ----
    #pragma unroll
    for (int mi = 0; mi < 2; mi++) {
        const int r0 = rowBase + wm * 32 + mi * 16 + (lane >> 2);
        #pragma unroll
        for (int nf = 0; nf < 4; nf++) {
            const int col = colBase + wn * 32 + nf * 8 + (lane & 3) * 2;
            if (EPI == 0) {
                if (r0 < M)
                    *(float2*)(Cf + (size_t)r0 * ldc + col) =
                        make_float2(c[mi][nf][0], c[mi][nf][1]);
                if (r0 + 8 < M)
                    *(float2*)(Cf + (size_t)(r0 + 8) * ldc + col) =
                        make_float2(c[mi][nf][2], c[mi][nf][3]);
            } else {
                const float bx = __ldg(bias + col), by = __ldg(bias + col + 1);
                #pragma unroll
                for (int h = 0; h < 2; h++) {
                    const int r = r0 + 8 * h;
                    if (r >= M) continue;
                    float v0 = tf32r(fmaxf(c[mi][nf][2 * h + 0] + bx, 0.f));
                    float v1 = tf32r(fmaxf(c[mi][nf][2 * h + 1] + by, 0.f));
                    *(float2*)(Cf + (size_t)r * ldc + col) = make_float2(v0, v1);
                }
            }
        }
    }
}

// ---------------------------------------------------------------------------
// Gather aggregation (float4 lanes, 2-edge unroll — round-12 proven config):
//   r = sum_e norm_e * t[src_e] + dinv[i]^2 * t[i] (+ bias) ; (relu)
//   EMIT_TF32: round output to tf32 (feeds next GEMM).
// ---------------------------------------------------------------------------
template <int D, bool RELU, bool EMIT_TF32, bool BIAS>
__global__ void agg_k(const float* __restrict__ t, float* __restrict__ outf,
                      const float* __restrict__ bias, int n)
{
    constexpr int L = D / 4;        // lanes per node
    constexpr int G = 256 / L;      // nodes per block
    const int lane = threadIdx.x % L;
    const int sub  = threadIdx.x / L;
    const int node = blockIdx.x * G + sub;
    if (node >= n) return;

    float4 b = make_float4(0.f, 0.f, 0.f, 0.f);
    if (BIAS) b = ((const float4*)bias)[lane];
    float di = g_dinv[node];
    float s  = di * di;
    float4 self = __ldg((const float4*)(t + (size_t)node * D) + lane);
    float4 a0 = make_float4(s * self.x + b.x, s * self.y + b.y,
                            s * self.z + b.z, s * self.w + b.w);
    float4 a1 = make_float4(0.f, 0.f, 0.f, 0.f);

    int e   = g_rowptr[node];
    int end = g_rowptr[node + 1];
    for (; e + 1 < end; e += 2) {
        int   s0 = g_csrc[e],  s1 = g_csrc[e + 1];
        float w0 = g_cnorm[e], w1 = g_cnorm[e + 1];
        float4 v0 = __ldg((const float4*)(t + (size_t)s0 * D) + lane);
        float4 v1 = __ldg((const float4*)(t + (size_t)s1 * D) + lane);
        a0.x += w0 * v0.x; a0.y += w0 * v0.y; a0.z += w0 * v0.z; a0.w += w0 * v0.w;
        a1.x += w1 * v1.x; a1.y += w1 * v1.y; a1.z += w1 * v1.z; a1.w += w1 * v1.w;
    }
    if (e < end) {
        float w0 = g_cnorm[e];
        float4 v0 = __ldg((const float4*)(t + (size_t)g_csrc[e] * D) + lane);
        a0.x += w0 * v0.x; a0.y += w0 * v0.y; a0.z += w0 * v0.z; a0.w += w0 * v0.w;
    }
    float4 r = make_float4(a0.x + a1.x, a0.y + a1.y, a0.z + a1.z, a0.w + a1.w);
    if (RELU) {
        r.x = fmaxf(r.x, 0.f); r.y = fmaxf(r.y, 0.f);
        r.z = fmaxf(r.z, 0.f); r.w = fmaxf(r.w, 0.f);
    }
    if (EMIT_TF32) {
        r.x = tf32r(r.x); r.y = tf32r(r.y);
        r.z = tf32r(r.z); r.w = tf32r(r.w);
    }
    ((float4*)(outf + (size_t)node * D))[lane] = r;
}

// ---------------------------------------------------------------------------
// Launch
// ---------------------------------------------------------------------------
extern "C" void kernel_launch(void* const* d_in, const int* in_sizes, int n_in,
                              void* d_out, int out_size)
{
    const float* x  = (const float*)d_in[0];
    const int*   ei = (const int*)  d_in[1];
    const float* ew = (const float*)d_in[2];
    const float* W0 = (const float*)d_in[3];
    const float* b0 = (const float*)d_in[4];
    const float* W1 = (const float*)d_in[5];
    const float* b1 = (const float*)d_in[6];
    const float* W2 = (const float*)d_in[7];
    const float* b2 = (const float*)d_in[8];
    float* out = (float*)d_out;

    const int* src = ei;
    const int* dst = ei + EE;

    float *bufA, *bufB, *xagg, *w0t, *w1t, *w2t;
    cudaGetSymbolAddress((void**)&bufA, g_bufA);
    cudaGetSymbolAddress((void**)&bufB, g_bufB);
    cudaGetSymbolAddress((void**)&xagg, g_xagg);
    cudaGetSymbolAddress((void**)&w0t, g_w0t);
    cudaGetSymbolAddress((void**)&w1t, g_w1t);
    cudaGetSymbolAddress((void**)&w2t, g_w2t);

    const int TB = 256;
    const int gN = (NN + TB - 1) / TB;
    const int gE = (EE + TB - 1) / TB;

    // ---- normalization + coalesced CSR build ----
    k_init<<<gN, TB>>>();
    k_deg_count<<<gE, TB>>>(dst, ew);
    k_blocksum_dinv<<<NBLK, 256>>>();
    k_scanblk<<<1, 512>>>();
    k_rowptr<<<NBLK, 256>>>();
    k_fill<<<gE, TB>>>(src, dst, ew);

    // ---- weight prep: transpose + tf32 round (single fused launch) ----
    const int WTOT = F_IN * HID + HID * HID + HID * NC;
    k_wsplit_all<<<(WTOT + 255) / 256, 256>>>(W0, W1, W2);

    const int gridM = (NN + 127) / 128;   // 782

    // ---- Layer 0:  h0 = relu(agg(x) @ W0 + b0)   [agg first: 128-dim gathers]
    agg_k<F_IN, false, true, false><<<(NN + 7) / 8, 256>>>(x, xagg, nullptr, NN);
    gemm_tf32<1><<<dim3(HID / 64, gridM), 256>>>(NN, F_IN, xagg, w0t, bufB, b0, HID);

    // ---- Layer 1:  h1 = relu(agg(h0 @ W1) + b1)
    gemm_tf32<0><<<dim3(HID / 64, gridM), 256>>>(NN, HID, bufB, w1t, bufA, nullptr, HID);
    agg_k<HID, true, true, true><<<(NN + 3) / 4, 256>>>(bufA, bufB, b1, NN);

    // ---- Layer 2:  out = agg(h1 @ W2) + b2   [64-dim gathers]
    gemm_tf32<0><<<dim3(NC / 64, gridM), 256>>>(NN, HID, bufB, w2t, bufA, nullptr, NC);
    agg_k<NC, false, false, true><<<(NN + 15) / 16, 256>>>(bufA, out, b2, NN);
}

// round 14
// speedup vs baseline: 1.4770x; 1.1244x over previous
#include <cuda_runtime.h>
#include <cuda_bf16.h>
#include <cuda_fp16.h>
#include <cstdint>
#include <math.h>

// Problem constants (fixed by the dataset)
#define NN   100000
#define EE   1600000
#define F_IN 128
#define HID  256
#define NC   64
#define NBLK ((NN + 255) / 256)   // 391

// ---------------------------------------------------------------------------
// Scratch (static __device__ arrays — no allocation allowed)
// ---------------------------------------------------------------------------
__device__ float g_deg[NN];
__device__ float g_dinv[NN];
__device__ int   g_wptr[NN];
__device__ int   g_rowptr[NN + 1];
__device__ int   g_blksum[NBLK];
__device__ int   g_blkoff[NBLK];
__device__ int   g_csrc[EE];
__device__ float g_cnorm[EE];
__device__ __align__(16) float  g_bufB[(size_t)NN * HID];   // GEMM fp32 (tf32) inputs
__device__ __align__(16) __half g_t16[(size_t)NN * HID];    // GEMM fp16 outputs (gather operand)
__device__ __align__(16) __half g_x16[(size_t)NN * F_IN];   // x in fp16 (gather operand)
__device__ __align__(16) float  g_xagg[(size_t)NN * F_IN];  // agg(x), tf32-rounded
__device__ __align__(16) float  g_w0t[HID * F_IN];          // W0^T, tf32-rounded
__device__ __align__(16) float  g_w1t[HID * HID];
__device__ __align__(16) float  g_w2t[NC * HID];

// ---------------------------------------------------------------------------
// PTX helpers (portable sm_80+; works on generic sm_103 target)
// ---------------------------------------------------------------------------
__device__ __forceinline__ uint32_t smem_u32(const void* p) {
    uint32_t a;
    asm("{ .reg .u64 t; cvta.to.shared.u64 t, %1; cvt.u32.u64 %0, t; }"
        : "=r"(a) : "l"(p));
    return a;
}

__device__ __forceinline__ float tf32r(float v) {
    uint32_t o;
    asm("cvt.rna.tf32.f32 %0, %1;" : "=r"(o) : "f"(v));
    return __uint_as_float(o);
}

#define LDSM4(r, addr) \
    asm volatile("ldmatrix.sync.aligned.m8n8.x4.shared.b16 {%0,%1,%2,%3}, [%4];" \
        : "=r"((r)[0]), "=r"((r)[1]), "=r"((r)[2]), "=r"((r)[3]) : "r"(addr))

#define MMA_TF32(c, a, b0, b1) \
    asm volatile("mma.sync.aligned.m16n8k8.row.col.f32.tf32.tf32.f32 " \
        "{%0,%1,%2,%3}, {%4,%5,%6,%7}, {%8,%9}, {%0,%1,%2,%3};" \
        : "+f"((c)[0]), "+f"((c)[1]), "+f"((c)[2]), "+f"((c)[3]) \
        : "r"((a)[0]), "r"((a)[1]), "r"((a)[2]), "r"((a)[3]), "r"(b0), "r"(b1))

#define CP16(dst, src, sz) \
    asm volatile("cp.async.cg.shared.global [%0], [%1], 16, %2;" \
        :: "r"(dst), "l"(src), "r"(sz) : "memory")
#define CP_COMMIT() asm volatile("cp.async.commit_group;" ::: "memory")
template <int N>
__device__ __forceinline__ void cp_wait() {
    asm volatile("cp.async.wait_group %0;" :: "n"(N) : "memory");
}

// ---------------------------------------------------------------------------
// Preprocessing kernels
// ---------------------------------------------------------------------------
__global__ void k_init()
{
    int i = blockIdx.x * blockDim.x + threadIdx.x;
    if (i < NN) { g_deg[i] = 1.0f; g_wptr[i] = 0; }
}

__global__ void k_deg_count(const int* __restrict__ dst, const float* __restrict__ w)
{
    int e = blockIdx.x * blockDim.x + threadIdx.x;
    if (e < EE) {
        int d = dst[e];
        atomicAdd(&g_deg[d], w[e]);
        atomicAdd(&g_wptr[d], 1);
    }
}

// blocksum of counts + dinv (fused: same index space)
__global__ void k_blocksum_dinv()
{
    __shared__ int sh[256];
    int i = blockIdx.x * 256 + threadIdx.x;
    sh[threadIdx.x] = (i < NN) ? g_wptr[i] : 0;
    if (i < NN) g_dinv[i] = rsqrtf(g_deg[i]);
    __syncthreads();
    for (int o = 128; o > 0; o >>= 1) {
        if (threadIdx.x < o) sh[threadIdx.x] += sh[threadIdx.x + o];
        __syncthreads();
    }
    if (threadIdx.x == 0) g_blksum[blockIdx.x] = sh[0];
}

__global__ void k_scanblk()
{
    __shared__ int sh[512];
    int t = threadIdx.x;
    int v = (t < NBLK) ? g_blksum[t] : 0;
    sh[t] = v;
    __syncthreads();
    for (int o = 1; o < 512; o <<= 1) {
        int a = (t >= o) ? sh[t - o] : 0;
        __syncthreads();
        sh[t] += a;
        __syncthreads();
    }
    if (t < NBLK) g_blkoff[t] = sh[t] - v;   // exclusive
}

__global__ void k_rowptr()
{
    __shared__ int sh[256];
    int i = blockIdx.x * 256 + threadIdx.x;
    int v = (i < NN) ? g_wptr[i] : 0;
    sh[threadIdx.x] = v;
    __syncthreads();
    for (int o = 1; o < 256; o <<= 1) {
        int a = (threadIdx.x >= o) ? sh[threadIdx.x - o] : 0;
        __syncthreads();
        sh[threadIdx.x] += a;
        __syncthreads();
    }
    if (i < NN) {
        int off = g_blkoff[blockIdx.x] + sh[threadIdx.x] - v;
        g_rowptr[i] = off;
        g_wptr[i]   = off;   // write cursor for fill
    }
    if (i == NN - 1) g_rowptr[NN] = EE;
}

__global__ void k_fill(const int* __restrict__ src, const int* __restrict__ dst,
                       const float* __restrict__ w)
{
    int e = blockIdx.x * blockDim.x + threadIdx.x;
    if (e < EE) {
        int s = src[e], d = dst[e];
        float nm = g_dinv[s] * w[e] * g_dinv[d];
        int slot = atomicAdd(&g_wptr[d], 1);
        g_csrc[slot]  = s;
        g_cnorm[slot] = nm;
    }
}

// All three weights: W[K,N] row-major -> Wt[N,K] K-major fp32, tf32-rounded
__global__ void k_wsplit_all(const float* __restrict__ W0,
                             const float* __restrict__ W1,
                             const float* __restrict__ W2)
{
    int i = blockIdx.x * blockDim.x + threadIdx.x;
    const float* W; float* wt; int K, Ncols, j;
    if (i < F_IN * HID)                   { W = W0; wt = g_w0t; K = F_IN; Ncols = HID; j = i; }
    else if (i < F_IN * HID + HID * HID)  { W = W1; wt = g_w1t; K = HID;  Ncols = HID; j = i - F_IN * HID; }
    else if (i < F_IN * HID + HID * HID + HID * NC)
                                          { W = W2; wt = g_w2t; K = HID;  Ncols = NC;  j = i - F_IN * HID - HID * HID; }
    else return;
    int n = j / K, k = j % K;
    wt[j] = tf32r(W[k * Ncols + n]);
}

// x fp32 -> fp16 (vectorized: 4 floats -> 4 halves per thread)
__global__ void k_x2h(const float* __restrict__ x, __half* __restrict__ xh)
{
    int i = blockIdx.x * blockDim.x + threadIdx.x;
    if (i < NN * F_IN / 4) {
        float4 v = ((const float4*)x)[i];
        __half2 h0 = __floats2half2_rn(v.x, v.y);
        __half2 h1 = __floats2half2_rn(v.z, v.w);
        ((__half2*)xh)[2 * i]     = h0;
        ((__half2*)xh)[2 * i + 1] = h1;
    }
}

// ---------------------------------------------------------------------------
// TF32 HMMA GEMM, cp.async double-buffered (round-13 proven structure).
//   C[M, ldc] = A[M, KT] @ Bt[Ncols, KT]^T ; A,Bt fp32 pre-rounded to tf32.
//   BM=128, BN=64, BK=32, 256 threads (warps 4m x 2n, warp tile 32x32).
//   Smem: 2 stages x 24576 B (static 48 KB), 128 B rows, XOR-16B swizzle.
//   EPI=0: fp16 store (gather operand). EPI=1: bias+relu+tf32 fp32 store.
// ---------------------------------------------------------------------------
template <int EPI>
__global__ void __launch_bounds__(256)
gemm_tf32(int M, int KT,
          const float* __restrict__ A, const float* __restrict__ B,
          float* __restrict__ Cf, __half* __restrict__ Ch,
          const float* __restrict__ bias, int ldc)
{
    constexpr int STG = 24576;          // A 128*128B + B 64*128B
    constexpr int OFF_A = 0, OFF_B = 16384;

    __shared__ __align__(16) char sm[2 * STG];
    const uint32_t smb = smem_u32(sm);

    const int tid  = threadIdx.x;
    const int lane = tid & 31, wid = tid >> 5;
    const int wm = wid & 3;             // 0..3  (m)
    const int wn = wid >> 2;            // 0..1  (n)
    const int rowBase = blockIdx.y * 128;
    const int colBase = blockIdx.x * 64;

    float c[2][4][4];
    #pragma unroll
    for (int mi = 0; mi < 2; mi++)
        #pragma unroll
        for (int nf = 0; nf < 4; nf++)
            #pragma unroll
            for (int j = 0; j < 4; j++) c[mi][nf][j] = 0.f;

    // ldmatrix lane addressing
    const int rr = lane & 7;
    const int qA = lane >> 3;
    const int cA = qA >> 1;                               // +0 / +1 (16B units)
    const int rA0 = wm * 32 + ((qA & 1) << 3) + rr;       // mi=0
    const int rA1 = rA0 + 16;                             // mi=1
    const uint32_t aOff0 = OFF_A + rA0 * 128; const int aX0 = rA0 & 7;
    const uint32_t aOff1 = OFF_A + rA1 * 128; const int aX1 = rA1 & 7;
    const int cB = (lane >> 3) & 1;
    const int rB0 = wn * 32 + ((lane >> 4) << 3) + rr;    // p=0 (n groups 0,1)
    const int rB1 = rB0 + 16;                             // p=1 (n groups 2,3)
    const uint32_t bOff0 = OFF_B + rB0 * 128; const int bX0 = rB0 & 7;
    const uint32_t bOff1 = OFF_B + rB1 * 128; const int bX1 = rB1 & 7;

    const int nchunk = KT >> 5;

    // ---- tile loader (cp.async): rows of 32 fp32 = 8 x 16B chunks, swizzled
    auto ld_tiles = [&](int st, int ch) {
        const uint32_t sb = smb + st * STG;
        const int k0 = ch * 32;
        #pragma unroll
        for (int i = tid; i < 1024; i += 256) {     // A: 128 rows x 8 chunks
            int row = i >> 3, cc = i & 7;
            int gr  = rowBase + row;
            uint32_t sz = (gr < M) ? 16u : 0u;
            int gra = (gr < M) ? gr : (M - 1);
            size_t go = (size_t)gra * KT + k0 + cc * 4;
            uint32_t d = row * 128 + ((cc ^ (row & 7)) << 4);
            CP16(sb + OFF_A + d, (const char*)(A + go), sz);
        }
        #pragma unroll
        for (int i = tid; i < 512; i += 256) {      // B: 64 rows x 8 chunks
            int row = i >> 3, cc = i & 7;
            size_t go = (size_t)(colBase + row) * KT + k0 + cc * 4;
            uint32_t d = row * 128 + ((cc ^ (row & 7)) << 4);
            CP16(sb + OFF_B + d, (const char*)(B + go), 16u);
        }
    };

    ld_tiles(0, 0);
    CP_COMMIT();

    for (int ch = 0; ch < nchunk; ch++) {
        if (ch + 1 < nchunk) { ld_tiles((ch + 1) & 1, ch + 1); CP_COMMIT(); }
        if (ch + 1 < nchunk) cp_wait<1>(); else cp_wait<0>();
        __syncthreads();

        const uint32_t sb = smb + (ch & 1) * STG;
        #pragma unroll
        for (int ks = 0; ks < 4; ks++) {
            uint32_t a[2][4], b[2][4];
            LDSM4(a[0], sb + aOff0 + (((2 * ks + cA) ^ aX0) << 4));
            LDSM4(a[1], sb + aOff1 + (((2 * ks + cA) ^ aX1) << 4));
            LDSM4(b[0], sb + bOff0 + (((2 * ks + cB) ^ bX0) << 4));
            LDSM4(b[1], sb + bOff1 + (((2 * ks + cB) ^ bX1) << 4));
            #pragma unroll
            for (int mi = 0; mi < 2; mi++)
                #pragma unroll
                for (int g = 0; g < 4; g++) {
                    const int p = g >> 1, s = (g & 1) * 2;
                    MMA_TF32(c[mi][g], a[mi], b[p][s], b[p][s + 1]);
                }
        }
        __syncthreads();
    }

    // ---- epilogue ----
    #pragma unroll
    for (int mi = 0; mi < 2; mi++) {
        const int r0 = rowBase + wm * 32 + mi * 16 + (lane >> 2);
        #pragma unroll
        for (int nf = 0; nf < 4; nf++) {
            const int col = colBase + wn * 32 + nf * 8 + (lane & 3) * 2;
            if (EPI == 0) {
                if (r0 < M)
                    *(__half2*)(Ch + (size_t)r0 * ldc + col) =
                        __floats2half2_rn(c[mi][nf][0], c[mi][nf][1]);
                if (r0 + 8 < M)
                    *(__half2*)(Ch + (size_t)(r0 + 8) * ldc + col) =
                        __floats2half2_rn(c[mi][nf][2], c[mi][nf][3]);
            } else {
                const float bx = __ldg(bias + col), by = __ldg(bias + col + 1);
                #pragma unroll
                for (int h = 0; h < 2; h++) {
                    const int r = r0 + 8 * h;
                    if (r >= M) continue;
                    float v0 = tf32r(fmaxf(c[mi][nf][2 * h + 0] + bx, 0.f));
                    float v1 = tf32r(fmaxf(c[mi][nf][2 * h + 1] + by, 0.f));
                    *(float2*)(Cf + (size_t)r * ldc + col) = make_float2(v0, v1);
                }
            }
        }
    }
}

// ---------------------------------------------------------------------------
// Gather aggregation over fp16 rows (half8 = 16B per lane, 2-edge unroll):
//   r = sum_e norm_e * t[src_e] + dinv[i]^2 * t[i] (+ bias) ; (relu)
//   Accumulate fp32; EMIT_TF32: round output to tf32 (feeds next GEMM).
// ---------------------------------------------------------------------------
__device__ __forceinline__ void h8_fma(float* acc, uint4 v, float w)
{
    float2 f0 = __half22float2(*(const __half2*)&v.x);
    float2 f1 = __half22float2(*((const __half2*)&v.x + 1));
    float2 f2 = __half22float2(*(const __half2*)&v.z);
    float2 f3 = __half22float2(*((const __half2*)&v.z + 1));
    acc[0] += w * f0.x; acc[1] += w * f0.y;
    acc[2] += w * f1.x; acc[3] += w * f1.y;
    acc[4] += w * f2.x; acc[5] += w * f2.y;
    acc[6] += w * f3.x; acc[7] += w * f3.y;
}

template <int D, bool RELU, bool EMIT_TF32, bool BIAS>
__global__ void agg_h(const __half* __restrict__ t, float* __restrict__ outf,
                      const float* __restrict__ bias, int n)
{
    constexpr int L = D / 8;        // lanes per node (8 dims per lane)
    constexpr int G = 256 / L;      // nodes per block
    const int lane = threadIdx.x % L;
    const int sub  = threadIdx.x / L;
    const int node = blockIdx.x * G + sub;
    if (node >= n) return;

    float a0[8] = {}, a1[8] = {};
    if (BIAS) {
        float4 b0 = ((const float4*)bias)[2 * lane];
        float4 b1 = ((const float4*)bias)[2 * lane + 1];
        a0[0] = b0.x; a0[1] = b0.y; a0[2] = b0.z; a0[3] = b0.w;
        a0[4] = b1.x; a0[5] = b1.y; a0[6] = b1.z; a0[7] = b1.w;
    }
    const float di = g_dinv[node];
    {   // self loop: dinv^2 * t[node]
        uint4 sv = __ldg((const uint4*)(t + (size_t)node * D) + lane);
        h8_fma(a0, sv, di * di);
    }

    int e   = g_rowptr[node];
    int end = g_rowptr[node + 1];
    for (; e + 1 < end; e += 2) {
        int   s0 = g_csrc[e],  s1 = g_csrc[e + 1];
        float w0 = g_cnorm[e], w1 = g_cnorm[e + 1];
        uint4 v0 = __ldg((const uint4*)(t + (size_t)s0 * D) + lane);
        uint4 v1 = __ldg((const uint4*)(t + (size_t)s1 * D) + lane);
        h8_fma(a0, v0, w0);
        h8_fma(a1, v1, w1);
    }
    if (e < end) {
        uint4 v0 = __ldg((const uint4*)(t + (size_t)g_csrc[e] * D) + lane);
        h8_fma(a0, v0, g_cnorm[e]);
    }

    float r[8];
    #pragma unroll
    for (int j = 0; j < 8; j++) {
        r[j] = a0[j] + a1[j];
        if (RELU) r[j] = fmaxf(r[j], 0.f);
        if (EMIT_TF32) r[j] = tf32r(r[j]);
    }
    float4* po = (float4*)(outf + (size_t)node * D + lane * 8);
    po[0] = make_float4(r[0], r[1], r[2], r[3]);
    po[1] = make_float4(r[4], r[5], r[6], r[7]);
}

// ---------------------------------------------------------------------------
// Launch
// ---------------------------------------------------------------------------
extern "C" void kernel_launch(void* const* d_in, const int* in_sizes, int n_in,
                              void* d_out, int out_size)
{
    const float* x  = (const float*)d_in[0];
    const int*   ei = (const int*)  d_in[1];
    const float* ew = (const float*)d_in[2];
    const float* W0 = (const float*)d_in[3];
    const float* b0 = (const float*)d_in[4];
    const float* W1 = (const float*)d_in[5];
    const float* b1 = (const float*)d_in[6];
    const float* W2 = (const float*)d_in[7];
    const float* b2 = (const float*)d_in[8];
    float* out = (float*)d_out;

    const int* src = ei;
    const int* dst = ei + EE;

    float *bufB, *xagg, *w0t, *w1t, *w2t;
    __half *t16, *x16;
    cudaGetSymbolAddress((void**)&bufB, g_bufB);
    cudaGetSymbolAddress((void**)&t16,  g_t16);
    cudaGetSymbolAddress((void**)&x16,  g_x16);
    cudaGetSymbolAddress((void**)&xagg, g_xagg);
    cudaGetSymbolAddress((void**)&w0t, g_w0t);
    cudaGetSymbolAddress((void**)&w1t, g_w1t);
    cudaGetSymbolAddress((void**)&w2t, g_w2t);

    const int TB = 256;
    const int gN = (NN + TB - 1) / TB;
    const int gE = (EE + TB - 1) / TB;

    // ---- normalization + coalesced CSR build ----
    k_init<<<gN, TB>>>();
    k_deg_count<<<gE, TB>>>(dst, ew);
    k_blocksum_dinv<<<NBLK, 256>>>();
    k_scanblk<<<1, 512>>>();
    k_rowptr<<<NBLK, 256>>>();
    k_fill<<<gE, TB>>>(src, dst, ew);

    // ---- operand prep: weights (transpose + tf32), x -> fp16 ----
    const int WTOT = F_IN * HID + HID * HID + HID * NC;
    k_wsplit_all<<<(WTOT + 255) / 256, 256>>>(W0, W1, W2);
    k_x2h<<<(NN * F_IN / 4 + 255) / 256, 256>>>(x, x16);

    const int gridM = (NN + 127) / 128;   // 782

    // ---- Layer 0:  h0 = relu(agg(x) @ W0 + b0)   [fp16 gathers, 128-dim]
    agg_h<F_IN, false, true, false><<<(NN + 15) / 16, 256>>>(x16, xagg, nullptr, NN);
    gemm_tf32<1><<<dim3(HID / 64, gridM), 256>>>(NN, F_IN, xagg, w0t, bufB, nullptr, b0, HID);

    // ---- Layer 1:  h1 = relu(agg(h0 @ W1) + b1)   [GEMM -> fp16, fp16 gathers]
    gemm_tf32<0><<<dim3(HID / 64, gridM), 256>>>(NN, HID, bufB, w1t, nullptr, t16, nullptr, HID);
    agg_h<HID, true, true, true><<<(NN + 7) / 8, 256>>>(t16, bufB, b1, NN);

    // ---- Layer 2:  out = agg(h1 @ W2) + b2   [GEMM -> fp16, 64-dim gathers]
    gemm_tf32<0><<<dim3(NC / 64, gridM), 256>>>(NN, HID, bufB, w2t, nullptr, t16, nullptr, NC);
    agg_h<NC, false, false, true><<<(NN + 31) / 32, 256>>>(t16, out, b2, NN);
}

// round 15
// speedup vs baseline: 1.8319x; 1.2403x over previous
#include <cuda_runtime.h>
#include <cuda_bf16.h>
#include <cuda_fp16.h>
#include <cstdint>
#include <math.h>

// Problem constants (fixed by the dataset)
#define NN   100000
#define EE   1600000
#define F_IN 128
#define HID  256
#define NC   64
#define NBLK ((NN + 255) / 256)   // 391

// ---------------------------------------------------------------------------
// Scratch (static __device__ arrays — no allocation allowed)
// ---------------------------------------------------------------------------
__device__ float g_deg[NN];
__device__ float g_dinv[NN];
__device__ int   g_wptr[NN];
__device__ int   g_rowptr[NN + 1];
__device__ int   g_blksum[NBLK];
__device__ int   g_blkoff[NBLK];
__device__ int   g_csrc[EE];
__device__ float g_cnorm[EE];
__device__ __align__(16) __half g_x16[(size_t)NN * F_IN];    // x in fp16
__device__ __align__(16) __half g_xagg[(size_t)NN * F_IN];   // agg(x) fp16
__device__ __align__(16) __half g_t16a[(size_t)NN * HID];    // fp16 ping
__device__ __align__(16) __half g_t16b[(size_t)NN * HID];    // fp16 pong
__device__ __align__(16) __half g_w0h[HID * F_IN];           // W^T fp16
__device__ __align__(16) __half g_w1h[HID * HID];
__device__ __align__(16) __half g_w2h[NC * HID];

// ---------------------------------------------------------------------------
// PTX helpers (portable sm_80+; works on generic sm_103 target)
// ---------------------------------------------------------------------------
__device__ __forceinline__ uint32_t smem_u32(const void* p) {
    uint32_t a;
    asm("{ .reg .u64 t; cvta.to.shared.u64 t, %1; cvt.u32.u64 %0, t; }"
        : "=r"(a) : "l"(p));
    return a;
}

#define LDSM4(r, addr) \
    asm volatile("ldmatrix.sync.aligned.m8n8.x4.shared.b16 {%0,%1,%2,%3}, [%4];" \
        : "=r"((r)[0]), "=r"((r)[1]), "=r"((r)[2]), "=r"((r)[3]) : "r"(addr))

#define MMA_F16(c, a, b0, b1) \
    asm volatile("mma.sync.aligned.m16n8k16.row.col.f32.f16.f16.f32 " \
        "{%0,%1,%2,%3}, {%4,%5,%6,%7}, {%8,%9}, {%0,%1,%2,%3};" \
        : "+f"((c)[0]), "+f"((c)[1]), "+f"((c)[2]), "+f"((c)[3]) \
        : "r"((a)[0]), "r"((a)[1]), "r"((a)[2]), "r"((a)[3]), "r"(b0), "r"(b1))

#define CP16(dst, src, sz) \
    asm volatile("cp.async.cg.shared.global [%0], [%1], 16, %2;" \
        :: "r"(dst), "l"(src), "r"(sz) : "memory")
#define CP_COMMIT() asm volatile("cp.async.commit_group;" ::: "memory")
template <int N>
__device__ __forceinline__ void cp_wait() {
    asm volatile("cp.async.wait_group %0;" :: "n"(N) : "memory");
}

// ---------------------------------------------------------------------------
// Preprocessing kernels
// ---------------------------------------------------------------------------
__global__ void k_init()
{
    int i = blockIdx.x * blockDim.x + threadIdx.x;
    if (i < NN) { g_deg[i] = 1.0f; g_wptr[i] = 0; }
}

__global__ void k_deg_count(const int* __restrict__ dst, const float* __restrict__ w)
{
    int e = blockIdx.x * blockDim.x + threadIdx.x;
    if (e < EE) {
        int d = dst[e];
        atomicAdd(&g_deg[d], w[e]);
        atomicAdd(&g_wptr[d], 1);
    }
}

// blocksum of counts + dinv (fused: same index space)
__global__ void k_blocksum_dinv()
{
    __shared__ int sh[256];
    int i = blockIdx.x * 256 + threadIdx.x;
    sh[threadIdx.x] = (i < NN) ? g_wptr[i] : 0;
    if (i < NN) g_dinv[i] = rsqrtf(g_deg[i]);
    __syncthreads();
    for (int o = 128; o > 0; o >>= 1) {
        if (threadIdx.x < o) sh[threadIdx.x] += sh[threadIdx.x + o];
        __syncthreads();
    }
    if (threadIdx.x == 0) g_blksum[blockIdx.x] = sh[0];
}

__global__ void k_scanblk()
{
    __shared__ int sh[512];
    int t = threadIdx.x;
    int v = (t < NBLK) ? g_blksum[t] : 0;
    sh[t] = v;
    __syncthreads();
    for (int o = 1; o < 512; o <<= 1) {
        int a = (t >= o) ? sh[t - o] : 0;
        __syncthreads();
        sh[t] += a;
        __syncthreads();
    }
    if (t < NBLK) g_blkoff[t] = sh[t] - v;   // exclusive
}

__global__ void k_rowptr()
{
    __shared__ int sh[256];
    int i = blockIdx.x * 256 + threadIdx.x;
    int v = (i < NN) ? g_wptr[i] : 0;
    sh[threadIdx.x] = v;
    __syncthreads();
    for (int o = 1; o < 256; o <<= 1) {
        int a = (threadIdx.x >= o) ? sh[threadIdx.x - o] : 0;
        __syncthreads();
        sh[threadIdx.x] += a;
        __syncthreads();
    }
    if (i < NN) {
        int off = g_blkoff[blockIdx.x] + sh[threadIdx.x] - v;
        g_rowptr[i] = off;
        g_wptr[i]   = off;   // write cursor for fill
    }
    if (i == NN - 1) g_rowptr[NN] = EE;
}

__global__ void k_fill(const int* __restrict__ src, const int* __restrict__ dst,
                       const float* __restrict__ w)
{
    int e = blockIdx.x * blockDim.x + threadIdx.x;
    if (e < EE) {
        int s = src[e], d = dst[e];
        float nm = g_dinv[s] * w[e] * g_dinv[d];
        int slot = atomicAdd(&g_wptr[d], 1);
        g_csrc[slot]  = s;
        g_cnorm[slot] = nm;
    }
}

// All three weights: W[K,N] row-major -> Wt[N,K] K-major fp16
__global__ void k_wsplit_all(const float* __restrict__ W0,
                             const float* __restrict__ W1,
                             const float* __restrict__ W2)
{
    int i = blockIdx.x * blockDim.x + threadIdx.x;
    const float* W; __half* wt; int K, Ncols, j;
    if (i < F_IN * HID)                   { W = W0; wt = g_w0h; K = F_IN; Ncols = HID; j = i; }
    else if (i < F_IN * HID + HID * HID)  { W = W1; wt = g_w1h; K = HID;  Ncols = HID; j = i - F_IN * HID; }
    else if (i < F_IN * HID + HID * HID + HID * NC)
                                          { W = W2; wt = g_w2h; K = HID;  Ncols = NC;  j = i - F_IN * HID - HID * HID; }
    else return;
    int n = j / K, k = j % K;
    wt[j] = __float2half(W[k * Ncols + n]);
}

// x fp32 -> fp16 (vectorized: 4 floats -> 4 halves per thread)
__global__ void k_x2h(const float* __restrict__ x, __half* __restrict__ xh)
{
    int i = blockIdx.x * blockDim.x + threadIdx.x;
    if (i < NN * F_IN / 4) {
        float4 v = ((const float4*)x)[i];
        ((__half2*)xh)[2 * i]     = __floats2half2_rn(v.x, v.y);
        ((__half2*)xh)[2 * i + 1] = __floats2half2_rn(v.z, v.w);
    }
}

// ---------------------------------------------------------------------------
// FP16 HMMA GEMM, cp.async double-buffered (round-12 proven skeleton, 1 term).
//   C[M, ldc] = A[M, KT] @ Bt[Ncols, KT]^T ; A,Bt fp16, fp32 accumulate.
//   BM=128, BN=64, BK=32, 256 threads (warps 4m x 2n, warp tile 32x32).
//   Smem: 2 stages x 12288 B (static 24 KB), 64 B rows, XOR-16B swizzle.
//   EPI=0: plain fp16 store. EPI=1: bias+relu+fp16 store.
// ---------------------------------------------------------------------------
template <int EPI>
__global__ void __launch_bounds__(256)
gemm_h(int M, int KT,
       const __half* __restrict__ A, const __half* __restrict__ B,
       __half* __restrict__ Ch, const float* __restrict__ bias, int ldc)
{
    constexpr int STG = 12288;          // A 128*64B + B 64*64B
    constexpr int OFF_A = 0, OFF_B = 8192;

    __shared__ __align__(16) char sm[2 * STG];
    const uint32_t smb = smem_u32(sm);

    const int tid  = threadIdx.x;
    const int lane = tid & 31, wid = tid >> 5;
    const int wm = wid & 3;             // 0..3  (m)
    const int wn = wid >> 2;            // 0..1  (n)
    const int rowBase = blockIdx.y * 128;
    const int colBase = blockIdx.x * 64;

    float c[2][4][4];
    #pragma unroll
    for (int mi = 0; mi < 2; mi++)
        #pragma unroll
        for (int nf = 0; nf < 4; nf++)
            #pragma unroll
            for (int j = 0; j < 4; j++) c[mi][nf][j] = 0.f;

    // ldmatrix per-lane rows + swizzle keys (round-12 proven addressing)
    const int lane15 = lane & 15;
    int  rA[2], rB[2];
    rA[0] = wm * 32 + lane15;  rA[1] = rA[0] + 16;
    rB[0] = wn * 32 + lane15;  rB[1] = rB[0] + 16;
    const int swA0 = (rA[0] >> 1) & 3, swA1 = (rA[1] >> 1) & 3;
    const int swB0 = (rB[0] >> 1) & 3, swB1 = (rB[1] >> 1) & 3;
    const int ccB  = lane >> 4;

    const int nchunk = KT >> 5;

    // ---- tile loader (cp.async): rows of 32 fp16 = 4 x 16B chunks, swizzled
    auto ld_tiles = [&](int st, int ch) {
        const uint32_t sb = smb + st * STG;
        const int k0 = ch * 32;
        #pragma unroll
        for (int i = tid; i < 512; i += 256) {      // A: 128 rows x 4 chunks
            int row = i >> 2, cc = i & 3;
            int gr  = rowBase + row;
            uint32_t sz = (gr < M) ? 16u : 0u;
            int gra = (gr < M) ? gr : (M - 1);
            size_t go = (size_t)gra * KT + k0 + cc * 8;
            uint32_t d = row * 64 + ((cc ^ ((row >> 1) & 3)) << 4);
            CP16(sb + OFF_A + d, (const char*)(A + go), sz);
        }
        {                                            // B: 64 rows x 4 chunks
            int row = tid >> 2, cc = tid & 3;
            size_t go = (size_t)(colBase + row) * KT + k0 + cc * 8;
            uint32_t d = row * 64 + ((cc ^ ((row >> 1) & 3)) << 4);
            CP16(sb + OFF_B + d, (const char*)(B + go), 16u);
        }
    };

    ld_tiles(0, 0);
    CP_COMMIT();

    for (int ch = 0; ch < nchunk; ch++) {
        if (ch + 1 < nchunk) { ld_tiles((ch + 1) & 1, ch + 1); CP_COMMIT(); }
        if (ch + 1 < nchunk) cp_wait<1>(); else cp_wait<0>();
        __syncthreads();

        const uint32_t sb = smb + (ch & 1) * STG;
        #pragma unroll
        for (int ks = 0; ks < 2; ks++) {
            const int cc = ccB + 2 * ks;
            uint32_t a[2][4], b[2][4];
            LDSM4(a[0], sb + OFF_A + rA[0] * 64 + ((cc ^ swA0) << 4));
            LDSM4(a[1], sb + OFF_A + rA[1] * 64 + ((cc ^ swA1) << 4));
            LDSM4(b[0], sb + OFF_B + rB[0] * 64 + ((cc ^ swB0) << 4));
            LDSM4(b[1], sb + OFF_B + rB[1] * 64 + ((cc ^ swB1) << 4));
            #pragma unroll
            for (int mi = 0; mi < 2; mi++)
                #pragma unroll
                for (int nf = 0; nf < 4; nf++) {
                    const int p = nf >> 1, s = nf & 1;
                    MMA_F16(c[mi][nf], a[mi], b[p][s], b[p][s + 2]);
                }
        }
        __syncthreads();
    }

    // ---- epilogue: fp16 store (optionally bias+relu) ----
    #pragma unroll
    for (int mi = 0; mi < 2; mi++) {
        const int r0 = rowBase + wm * 32 + mi * 16 + (lane >> 2);
        #pragma unroll
        for (int nf = 0; nf < 4; nf++) {
            const int col = colBase + wn * 32 + nf * 8 + (lane & 3) * 2;
            float bx = 0.f, by = 0.f;
            if (EPI == 1) { bx = __ldg(bias + col); by = __ldg(bias + col + 1); }
            #pragma unroll
            for (int h = 0; h < 2; h++) {
                const int r = r0 + 8 * h;
                if (r >= M) continue;
                float v0 = c[mi][nf][2 * h + 0];
                float v1 = c[mi][nf][2 * h + 1];
                if (EPI == 1) {
                    v0 = fmaxf(v0 + bx, 0.f);
                    v1 = fmaxf(v1 + by, 0.f);
                }
                *(__half2*)(Ch + (size_t)r * ldc + col) = __floats2half2_rn(v0, v1);
            }
        }
    }
}

// ---------------------------------------------------------------------------
// Gather aggregation over fp16 rows (half8 = 16B per lane, 2-edge unroll):
//   r = sum_e norm_e * t[src_e] + dinv[i]^2 * t[i] (+ bias) ; (relu)
//   Accumulate fp32. EMIT_H: store fp16 (GEMM input); else fp32.
// ---------------------------------------------------------------------------
__device__ __forceinline__ void h8_fma(float* acc, uint4 v, float w)
{
    float2 f0 = __half22float2(*(const __half2*)&v.x);
    float2 f1 = __half22float2(*((const __half2*)&v.x + 1));
    float2 f2 = __half22float2(*(const __half2*)&v.z);
    float2 f3 = __half22float2(*((const __half2*)&v.z + 1));
    acc[0] += w * f0.x; acc[1] += w * f0.y;
    acc[2] += w * f1.x; acc[3] += w * f1.y;
    acc[4] += w * f2.x; acc[5] += w * f2.y;
    acc[6] += w * f3.x; acc[7] += w * f3.y;
}

template <int D, bool RELU, bool EMIT_H, bool BIAS>
__global__ void agg_h(const __half* __restrict__ t,
                      __half* __restrict__ outh, float* __restrict__ outf,
                      const float* __restrict__ bias, int n)
{
    constexpr int L = D / 8;        // lanes per node (8 dims per lane)
    constexpr int G = 256 / L;      // nodes per block
    const int lane = threadIdx.x % L;
    const int sub  = threadIdx.x / L;
    const int node = blockIdx.x * G + sub;
    if (node >= n) return;

    float a0[8] = {}, a1[8] = {};
    if (BIAS) {
        float4 b0 = ((const float4*)bias)[2 * lane];
        float4 b1 = ((const float4*)bias)[2 * lane + 1];
        a0[0] = b0.x; a0[1] = b0.y; a0[2] = b0.z; a0[3] = b0.w;
        a0[4] = b1.x; a0[5] = b1.y; a0[6] = b1.z; a0[7] = b1.w;
    }
    const float di = g_dinv[node];
    {   // self loop: dinv^2 * t[node]
        uint4 sv = __ldg((const uint4*)(t + (size_t)node * D) + lane);
        h8_fma(a0, sv, di * di);
    }

    int e   = g_rowptr[node];
    int end = g_rowptr[node + 1];
    for (; e + 1 < end; e += 2) {
        int   s0 = g_csrc[e],  s1 = g_csrc[e + 1];
        float w0 = g_cnorm[e], w1 = g_cnorm[e + 1];
        uint4 v0 = __ldg((const uint4*)(t + (size_t)s0 * D) + lane);
        uint4 v1 = __ldg((const uint4*)(t + (size_t)s1 * D) + lane);
        h8_fma(a0, v0, w0);
        h8_fma(a1, v1, w1);
    }
    if (e < end) {
        uint4 v0 = __ldg((const uint4*)(t + (size_t)g_csrc[e] * D) + lane);
        h8_fma(a0, v0, g_cnorm[e]);
    }

    float r[8];
    #pragma unroll
    for (int j = 0; j < 8; j++) {
        r[j] = a0[j] + a1[j];
        if (RELU) r[j] = fmaxf(r[j], 0.f);
    }
    if (EMIT_H) {
        uint4 o;
        *(__half2*)&o.x       = __floats2half2_rn(r[0], r[1]);
        *((__half2*)&o.x + 1) = __floats2half2_rn(r[2], r[3]);
        *(__half2*)&o.z       = __floats2half2_rn(r[4], r[5]);
        *((__half2*)&o.z + 1) = __floats2half2_rn(r[6], r[7]);
        *((uint4*)(outh + (size_t)node * D + lane * 8)) = o;
    } else {
        float4* po = (float4*)(outf + (size_t)node * D + lane * 8);
        po[0] = make_float4(r[0], r[1], r[2], r[3]);
        po[1] = make_float4(r[4], r[5], r[6], r[7]);
    }
}

// ---------------------------------------------------------------------------
// Launch
// ---------------------------------------------------------------------------
extern "C" void kernel_launch(void* const* d_in, const int* in_sizes, int n_in,
                              void* d_out, int out_size)
{
    const float* x  = (const float*)d_in[0];
    const int*   ei = (const int*)  d_in[1];
    const float* ew = (const float*)d_in[2];
    const float* W0 = (const float*)d_in[3];
    const float* b0 = (const float*)d_in[4];
    const float* W1 = (const float*)d_in[5];
    const float* b1 = (const float*)d_in[6];
    const float* W2 = (const float*)d_in[7];
    const float* b2 = (const float*)d_in[8];
    float* out = (float*)d_out;

    const int* src = ei;
    const int* dst = ei + EE;

    __half *x16, *xagg, *t16a, *t16b, *w0h, *w1h, *w2h;
    cudaGetSymbolAddress((void**)&x16,  g_x16);
    cudaGetSymbolAddress((void**)&xagg, g_xagg);
    cudaGetSymbolAddress((void**)&t16a, g_t16a);
    cudaGetSymbolAddress((void**)&t16b, g_t16b);
    cudaGetSymbolAddress((void**)&w0h, g_w0h);
    cudaGetSymbolAddress((void**)&w1h, g_w1h);
    cudaGetSymbolAddress((void**)&w2h, g_w2h);

    const int TB = 256;
    const int gN = (NN + TB - 1) / TB;
    const int gE = (EE + TB - 1) / TB;

    // ---- normalization + coalesced CSR build ----
    k_init<<<gN, TB>>>();
    k_deg_count<<<gE, TB>>>(dst, ew);
    k_blocksum_dinv<<<NBLK, 256>>>();
    k_scanblk<<<1, 512>>>();
    k_rowptr<<<NBLK, 256>>>();
    k_fill<<<gE, TB>>>(src, dst, ew);

    // ---- operand prep: weights (transpose + fp16), x -> fp16 ----
    const int WTOT = F_IN * HID + HID * HID + HID * NC;
    k_wsplit_all<<<(WTOT + 255) / 256, 256>>>(W0, W1, W2);
    k_x2h<<<(NN * F_IN / 4 + 255) / 256, 256>>>(x, x16);

    const int gridM = (NN + 127) / 128;   // 782

    // ---- Layer 0:  h0 = relu(agg(x) @ W0 + b0)   [fp16 end-to-end]
    agg_h<F_IN, false, true, false><<<(NN + 15) / 16, 256>>>(
        x16, xagg, nullptr, nullptr, NN);
    gemm_h<1><<<dim3(HID / 64, gridM), 256>>>(NN, F_IN, xagg, w0h, t16a, b0, HID);

    // ---- Layer 1:  h1 = relu(agg(h0 @ W1) + b1)
    gemm_h<0><<<dim3(HID / 64, gridM), 256>>>(NN, HID, t16a, w1h, t16b, nullptr, HID);
    agg_h<HID, true, true, true><<<(NN + 7) / 8, 256>>>(
        t16b, t16a, nullptr, b1, NN);

    // ---- Layer 2:  out = agg(h1 @ W2) + b2   [fp32 out]
    gemm_h<0><<<dim3(NC / 64, gridM), 256>>>(NN, HID, t16a, w2h, t16b, nullptr, NC);
    agg_h<NC, false, false, true><<<(NN + 31) / 32, 256>>>(
        t16b, nullptr, out, b2, NN);
}